// round 10
// baseline (speedup 1.0000x reference)
#include <cuda_runtime.h>
#include <cuda_bf16.h>
#include <cstdint>

// ------------------------------------------------------------------
// Problem constants
// ------------------------------------------------------------------
constexpr int N_ROWS = 8192;
constexpr int DIM    = 1024;          // elements per row; int8 row = 1024 B
constexpr float SQRT_INV_TEMP = 2.23606797749978969f;   // sqrt(1/0.2)

constexpr int TM = 128;               // CTA tile rows
constexpr int TN = 128;               // CTA tile cols
constexpr int TKB = 128;              // bytes of K per stage (= 128 int8 elems)
constexpr int STAGES  = 3;
constexpr int THREADS = 256;          // 8 warps, 2 (M) x 4 (N)
constexpr int NKC = DIM / TKB;        // 8 K chunks (int8)

constexpr int A_BYTES   = TM * TKB;               // 16 KB
constexpr int B_BYTES   = TN * TKB;               // 16 KB
constexpr int STG_BYTES = A_BYTES + B_BYTES;      // 32 KB
constexpr int SMEM_BYTES = STAGES * STG_BYTES;    // 96 KB

constexpr int NTILE   = N_ROWS / TM;              // 64
constexpr int NTRI    = NTILE * (NTILE + 1) / 2;  // 2080 upper-tri tiles
constexpr int NSTRIPE = N_ROWS / 32;              // 256 scratch slots per row
constexpr int NRL_CTAS = N_ROWS / 32;             // 256 rowloss CTAs

// ------------------------------------------------------------------
// Device scratch (static globals: allocation-free)
// Slot coverage per row (tr = row's tile): dir-1 writes tn*4+{0..3} for tn>=tr;
// dir-2 writes tm*4+{0,2} (values) and tm*4+{1,3} (zeros) for tm<tr
// -> every slot written exactly once; no zero-fill kernel.
// ------------------------------------------------------------------
__device__ int8_t g_q[(size_t)N_ROWS * DIM];          // per-row int8 quantized x-hat
__device__ float  g_scale[N_ROWS];                    // sqrt(5)*amax/(127*norm)
__device__ float  g_ps[NSTRIPE * N_ROWS];             // partial sum exp(sim)
__device__ float  g_pa[NSTRIPE * N_ROWS];             // partial sum lbl*sim
__device__ float  g_pb[NSTRIPE * N_ROWS];             // partial sum lbl
__device__ float  g_blocksum[NRL_CTAS];               // per-rowloss-CTA loss partials

// ------------------------------------------------------------------
// PTX helpers
// ------------------------------------------------------------------
__device__ __forceinline__ uint32_t smem_u32(const void* p) {
    uint32_t a;
    asm("{ .reg .u64 t; cvta.to.shared.u64 t, %1; cvt.u32.u64 %0, t; }" : "=r"(a) : "l"(p));
    return a;
}

__device__ __forceinline__ void cp_async16(uint32_t dst, const void* src) {
    asm volatile("{ .reg .u64 g; cvta.to.global.u64 g, %1; "
                 "cp.async.cg.shared.global [%0], [g], 16; }"
                 :: "r"(dst), "l"(src) : "memory");
}
#define CP_COMMIT() asm volatile("cp.async.commit_group;" ::: "memory")
#define CP_WAIT(N)  asm volatile("cp.async.wait_group %0;" :: "n"(N) : "memory")

#define LDSM_X4(R0, R1, R2, R3, ADDR) \
    asm volatile("ldmatrix.sync.aligned.m8n8.x4.shared.b16 {%0,%1,%2,%3}, [%4];" \
                 : "=r"(R0), "=r"(R1), "=r"(R2), "=r"(R3) : "r"(ADDR))

// s8 IMMA: D(s32) += A(16x32 s8) * B(8x32 s8)^T
__device__ __forceinline__ void mma_s8(int* d, const uint32_t* a, const uint32_t* b) {
    asm volatile(
        "mma.sync.aligned.m16n8k32.row.col.s32.s8.s8.s32 "
        "{%0,%1,%2,%3}, {%4,%5,%6,%7}, {%8,%9}, {%0,%1,%2,%3};"
        : "+r"(d[0]), "+r"(d[1]), "+r"(d[2]), "+r"(d[3])
        : "r"(a[0]), "r"(a[1]), "r"(a[2]), "r"(a[3]), "r"(b[0]), "r"(b[1]));
}

// ------------------------------------------------------------------
// Kernel 1: row-normalize + per-row symmetric int8 quantization.
//   q = round(x * 127/amax);  g_scale = sqrt(5)*amax/(127*norm)
//   => sim/T = (q_i . q_j) * g_scale[i] * g_scale[j]
// ------------------------------------------------------------------
__global__ __launch_bounds__(256) void coref_norm_kernel(const float* __restrict__ e) {
    const int row = blockIdx.x, t = threadIdx.x;
    const float* r = e + (size_t)row * DIM;
    float x0 = r[t], x1 = r[t + 256], x2 = r[t + 512], x3 = r[t + 768];
    float ss = x0 * x0 + x1 * x1 + x2 * x2 + x3 * x3;
    float mx = fmaxf(fmaxf(fabsf(x0), fabsf(x1)), fmaxf(fabsf(x2), fabsf(x3)));
    #pragma unroll
    for (int o = 16; o > 0; o >>= 1) {
        ss += __shfl_xor_sync(0xffffffffu, ss, o);
        mx = fmaxf(mx, __shfl_xor_sync(0xffffffffu, mx, o));
    }
    __shared__ float ws[8], wm[8];
    if ((t & 31) == 0) { ws[t >> 5] = ss; wm[t >> 5] = mx; }
    __syncthreads();
    float tot = ws[0] + ws[1] + ws[2] + ws[3] + ws[4] + ws[5] + ws[6] + ws[7];
    float amax = fmaxf(fmaxf(fmaxf(wm[0], wm[1]), fmaxf(wm[2], wm[3])),
                       fmaxf(fmaxf(wm[4], wm[5]), fmaxf(wm[6], wm[7])));
    amax = fmaxf(amax, 1e-20f);
    const float norm = fmaxf(sqrtf(tot), 1e-8f);
    const float qs = 127.0f / amax;
    if (t == 0) g_scale[row] = SQRT_INV_TEMP * amax / (127.0f * norm);
    int8_t* op = g_q + (size_t)row * DIM;
    op[t]       = (int8_t)__float2int_rn(x0 * qs);
    op[t + 256] = (int8_t)__float2int_rn(x1 * qs);
    op[t + 512] = (int8_t)__float2int_rn(x2 * qs);
    op[t + 768] = (int8_t)__float2int_rn(x3 * qs);
}

// ------------------------------------------------------------------
// Kernel 2: fused upper-triangular tile GEMM (mma.sync s8, K=32/instr)
//           + two-direction softmax/label epilogue (sim is symmetric)
// ------------------------------------------------------------------
__device__ __forceinline__ void load_stage(uint32_t sbuf, int row_a, int row_b,
                                           int kc, int tid) {
    const int8_t* gA = g_q + (size_t)row_a * DIM + kc * TKB;
    #pragma unroll
    for (int i = 0; i < 4; ++i) {                 // A: 128 rows x 8 chunks (16B)
        int id = tid + (i << 8);
        int r = id >> 3, c = id & 7;
        uint32_t sw = (uint32_t)(r * 128) + (uint32_t)((c ^ (r & 7)) << 4);
        cp_async16(sbuf + sw, gA + (size_t)r * DIM + c * 16);
    }
    const int8_t* gB = g_q + (size_t)row_b * DIM + kc * TKB;
    uint32_t bb = sbuf + A_BYTES;
    #pragma unroll
    for (int i = 0; i < 4; ++i) {                 // B: 128 rows x 8 chunks
        int id = tid + (i << 8);
        int r = id >> 3, c = id & 7;
        uint32_t sw = (uint32_t)(r * 128) + (uint32_t)((c ^ (r & 7)) << 4);
        cp_async16(bb + sw, gB + (size_t)r * DIM + c * 16);
    }
}

__global__ __launch_bounds__(THREADS, 2)
void coref_main_kernel(const float* __restrict__ labels) {
    extern __shared__ char smem_raw[];
    const uint32_t sb = smem_u32(smem_raw);

    const int tid  = threadIdx.x;
    const int lane = tid & 31;
    const int warp = tid >> 5;
    const int warp_m = warp & 1;        // 0..1 -> 64-row half
    const int warp_n = warp >> 1;       // 0..3 -> 32-col stripe

    // Decode blockIdx.x -> upper-triangular (tm, tn), tm <= tn
    int brem = blockIdx.x, tm = 0;
    while (brem >= NTILE - tm) { brem -= NTILE - tm; ++tm; }
    const int tn = tm + brem;
    const int row0 = tm * TM;
    const int col0 = tn * TN;
    const bool offdiag = (tm != tn);

    // Prologue: prefetch stages 0,1
    load_stage(sb,              row0, col0, 0, tid); CP_COMMIT();
    load_stage(sb + STG_BYTES,  row0, col0, 1, tid); CP_COMMIT();

    int acc[4][4][4];                            // [mi][ni][frag], s32
    #pragma unroll
    for (int mi = 0; mi < 4; ++mi)
        #pragma unroll
        for (int ni = 0; ni < 4; ++ni)
            #pragma unroll
            for (int j = 0; j < 4; ++j) acc[mi][ni][j] = 0;

    // ldmatrix lane addressing (16-byte chunks; same pattern as bf16 version)
    const int a_row_in = (lane & 7) + ((lane >> 3) & 1) * 8;
    const int a_hi     = lane >> 4;
    const int b_row_in = (lane & 7) + (lane >> 4) * 8;
    const int b_hi     = (lane >> 3) & 1;

    int a_rowbyte[4], a_rx[4];
    #pragma unroll
    for (int mi = 0; mi < 4; ++mi) {
        int r = warp_m * 64 + mi * 16 + a_row_in;
        a_rowbyte[mi] = r * 128;
        a_rx[mi] = r & 7;
    }
    int b_rowbyte[2], b_rx[2];
    #pragma unroll
    for (int g = 0; g < 2; ++g) {
        int r = warp_n * 32 + g * 16 + b_row_in;
        b_rowbyte[g] = r * 128;
        b_rx[g] = r & 7;
    }

    for (int kc = 0; kc < NKC; ++kc) {
        if (kc == NKC - 1) { CP_WAIT(0); } else { CP_WAIT(1); }
        __syncthreads();

        if (kc + 2 < NKC) {
            load_stage(sb + ((kc + 2) % STAGES) * STG_BYTES, row0, col0, kc + 2, tid);
            CP_COMMIT();
        }

        const uint32_t sA = sb + (kc % STAGES) * STG_BYTES;
        const uint32_t sB = sA + A_BYTES;

        #pragma unroll
        for (int kk = 0; kk < 4; ++kk) {          // 4 x K=32 per 128B chunk
            const int kk2 = kk * 2;               // 16B-chunk index
            uint32_t Af[4][4], Bf[4][2];
            #pragma unroll
            for (int mi = 0; mi < 4; ++mi) {
                uint32_t addr = sA + a_rowbyte[mi]
                              + (uint32_t)(((kk2 + a_hi) ^ a_rx[mi]) << 4);
                LDSM_X4(Af[mi][0], Af[mi][1], Af[mi][2], Af[mi][3], addr);
            }
            #pragma unroll
            for (int g = 0; g < 2; ++g) {
                uint32_t q0, q1, q2, q3;
                uint32_t addr = sB + b_rowbyte[g]
                              + (uint32_t)(((kk2 + b_hi) ^ b_rx[g]) << 4);
                LDSM_X4(q0, q1, q2, q3, addr);
                Bf[g * 2 + 0][0] = q0; Bf[g * 2 + 0][1] = q1;
                Bf[g * 2 + 1][0] = q2; Bf[g * 2 + 1][1] = q3;
            }
            #pragma unroll
            for (int mi = 0; mi < 4; ++mi)
                #pragma unroll
                for (int ni = 0; ni < 4; ++ni)
                    mma_s8(acc[mi][ni], Af[mi], Bf[ni]);
        }
    }

    // ---------------- epilogue ----------------
    // Fragment: rows qrow, qrow+8; cols 2*(lane%4), +1
    const int qrow = lane >> 2;        // 0..7
    const int qcol = (lane & 3) * 2;   // 0,2,4,6

    // ---- pass 1: row partials for m-block rows (dir-1) ----
    {
        const int stripe = tn * 4 + warp_n;
        #pragma unroll
        for (int mi = 0; mi < 4; ++mi) {
            #pragma unroll
            for (int h = 0; h < 2; ++h) {
                const int grow = row0 + warp_m * 64 + mi * 16 + qrow + h * 8;
                const float rs = g_scale[grow];
                const float* lrow = labels + (size_t)grow * N_ROWS + col0 + warp_n * 32;
                float s = 0.f, a = 0.f, b = 0.f;
                #pragma unroll
                for (int ni = 0; ni < 4; ++ni) {
                    const int gcol = col0 + warp_n * 32 + ni * 8 + qcol;
                    float2 lv = __ldcs((const float2*)(lrow + ni * 8 + qcol));
                    float2 cs = *(const float2*)(g_scale + gcol);
                    float s0 = (float)acc[mi][ni][h * 2 + 0] * (rs * cs.x);
                    float s1 = (float)acc[mi][ni][h * 2 + 1] * (rs * cs.y);
                    if (gcol != grow) {                  // only binds on diag tiles
                        s += __expf(s0);
                        a = fmaf(lv.x, s0, a);
                        b += lv.x;
                    }
                    if (gcol + 1 != grow) {
                        s += __expf(s1);
                        a = fmaf(lv.y, s1, a);
                        b += lv.y;
                    }
                }
                s += __shfl_xor_sync(0xffffffffu, s, 1);
                s += __shfl_xor_sync(0xffffffffu, s, 2);
                a += __shfl_xor_sync(0xffffffffu, a, 1);
                a += __shfl_xor_sync(0xffffffffu, a, 2);
                b += __shfl_xor_sync(0xffffffffu, b, 1);
                b += __shfl_xor_sync(0xffffffffu, b, 2);
                if ((lane & 3) == 0) {
                    g_ps[stripe * N_ROWS + grow] = s;
                    g_pa[stripe * N_ROWS + grow] = a;
                    g_pb[stripe * N_ROWS + grow] = b;
                }
            }
        }
    }

    // ---- pass 2 (off-diag only): column partials for n-block rows (dir-2) ----
    if (offdiag) {
        const int slot  = tm * 4 + warp_m * 2;
        const int zslot = slot + 1;                 // hole slot: zero-filled here
        #pragma unroll
        for (int ni = 0; ni < 4; ++ni) {
            const int gc0 = col0 + warp_n * 32 + ni * 8 + qcol;   // output rows gc0, gc0+1
            const float2 cs = *(const float2*)(g_scale + gc0);
            const float* lc0 = labels + (size_t)gc0 * N_ROWS;
            const float* lc1 = lc0 + N_ROWS;
            float s0 = 0.f, s1 = 0.f, a0 = 0.f, a1 = 0.f, b0 = 0.f, b1 = 0.f;
            #pragma unroll
            for (int mi = 0; mi < 4; ++mi) {
                #pragma unroll
                for (int h = 0; h < 2; ++h) {
                    const int grow = row0 + warp_m * 64 + mi * 16 + h * 8 + qrow;
                    const float rsv = g_scale[grow];
                    float v0 = (float)acc[mi][ni][h * 2 + 0] * (rsv * cs.x);
                    float v1 = (float)acc[mi][ni][h * 2 + 1] * (rsv * cs.y);
                    float l0 = __ldcs(lc0 + grow);     // lbl[gc0][grow]
                    float l1 = __ldcs(lc1 + grow);     // lbl[gc0+1][grow]
                    s0 += __expf(v0);
                    s1 += __expf(v1);
                    a0 = fmaf(l0, v0, a0);
                    a1 = fmaf(l1, v1, a1);
                    b0 += l0;
                    b1 += l1;
                }
            }
            #pragma unroll
            for (int o = 4; o <= 16; o <<= 1) {
                s0 += __shfl_xor_sync(0xffffffffu, s0, o);
                s1 += __shfl_xor_sync(0xffffffffu, s1, o);
                a0 += __shfl_xor_sync(0xffffffffu, a0, o);
                a1 += __shfl_xor_sync(0xffffffffu, a1, o);
                b0 += __shfl_xor_sync(0xffffffffu, b0, o);
                b1 += __shfl_xor_sync(0xffffffffu, b1, o);
            }
            if (qrow == 0) {
                g_ps[slot * N_ROWS + gc0]     = s0;
                g_ps[slot * N_ROWS + gc0 + 1] = s1;
                g_pa[slot * N_ROWS + gc0]     = a0;
                g_pa[slot * N_ROWS + gc0 + 1] = a1;
                g_pb[slot * N_ROWS + gc0]     = b0;
                g_pb[slot * N_ROWS + gc0 + 1] = b1;
                // zero-fill the hole slot (replaces a standalone zero kernel)
                g_ps[zslot * N_ROWS + gc0]     = 0.f;
                g_ps[zslot * N_ROWS + gc0 + 1] = 0.f;
                g_pa[zslot * N_ROWS + gc0]     = 0.f;
                g_pa[zslot * N_ROWS + gc0 + 1] = 0.f;
                g_pb[zslot * N_ROWS + gc0]     = 0.f;
                g_pb[zslot * N_ROWS + gc0 + 1] = 0.f;
            }
        }
    }
}

// ------------------------------------------------------------------
// Kernel 3: per-row reduction of the 256 stripe partials + per-CTA loss partial
// ------------------------------------------------------------------
__global__ __launch_bounds__(256) void coref_rowloss_kernel() {
    const int rlane = threadIdx.x & 31;
    const int grp   = threadIdx.x >> 5;            // 0..7
    const int row   = blockIdx.x * 32 + rlane;
    float S = 0.f, A = 0.f, B = 0.f;
    #pragma unroll 8
    for (int k = 0; k < 32; ++k) {
        const int t = grp * 32 + k;
        S += g_ps[t * N_ROWS + row];
        A += g_pa[t * N_ROWS + row];
        B += g_pb[t * N_ROWS + row];
    }
    __shared__ float ss[8][32], sa[8][32], sb2[8][32];
    ss[grp][rlane] = S; sa[grp][rlane] = A; sb2[grp][rlane] = B;
    __syncthreads();
    if (grp == 0) {
        float St = 0.f, At = 0.f, Bt = 0.f;
        #pragma unroll
        for (int g = 0; g < 8; ++g) {
            St += ss[g][rlane]; At += sa[g][rlane]; Bt += sb2[g][rlane];
        }
        // loss_i = lse_i * B_i - A_i   (no max shift: |sim| <= ~5)
        float loss = logf(St) * Bt - At;
        #pragma unroll
        for (int o = 16; o > 0; o >>= 1) loss += __shfl_xor_sync(0xffffffffu, loss, o);
        if (rlane == 0) g_blocksum[blockIdx.x] = loss;
    }
}

// ------------------------------------------------------------------
// Kernel 4: deterministic fixed-tree reduce of 256 block partials -> mean
// ------------------------------------------------------------------
__global__ __launch_bounds__(256) void coref_final_kernel(float* __restrict__ out) {
    __shared__ float sm[256];
    const int t = threadIdx.x;
    sm[t] = g_blocksum[t];
    __syncthreads();
    #pragma unroll
    for (int s = 128; s > 0; s >>= 1) {
        if (t < s) sm[t] += sm[t + s];
        __syncthreads();
    }
    if (t == 0) out[0] = sm[0] * (1.0f / (float)N_ROWS);
}

// ------------------------------------------------------------------
// Launcher (graph-capturable)
// ------------------------------------------------------------------
extern "C" void kernel_launch(void* const* d_in, const int* in_sizes, int n_in,
                              void* d_out, int out_size) {
    const float* embs   = (const float*)d_in[0];
    const float* labels = (const float*)d_in[1];
    if (n_in >= 2 && in_sizes[0] == N_ROWS * N_ROWS) {  // defensive input-order check
        const float* tmp = embs; embs = labels; labels = tmp;
    }
    float* out = (float*)d_out;

    cudaFuncSetAttribute(coref_main_kernel,
                         cudaFuncAttributeMaxDynamicSharedMemorySize, SMEM_BYTES);

    coref_norm_kernel<<<N_ROWS, 256>>>(embs);
    coref_main_kernel<<<NTRI, THREADS, SMEM_BYTES>>>(labels);
    coref_rowloss_kernel<<<NRL_CTAS, 256>>>();
    coref_final_kernel<<<1, 256>>>(out);
}

// round 11
// speedup vs baseline: 1.9524x; 1.9524x over previous
#include <cuda_runtime.h>
#include <cuda_bf16.h>
#include <cstdint>

// ------------------------------------------------------------------
// Problem constants
// ------------------------------------------------------------------
constexpr int N_ROWS = 8192;
constexpr int DIM    = 1024;
constexpr float SQRT_INV_TEMP = 2.23606797749978969f;   // sqrt(1/0.2)

constexpr int TM = 128;               // CTA tile rows
constexpr int TN = 128;               // CTA tile cols
constexpr int TK = 64;                // bf16 K elems per stage (128 B rows)
constexpr int STAGES  = 3;
constexpr int THREADS = 256;          // 8 warps, 2 (M) x 4 (N)
constexpr int NKC = DIM / TK;         // 16 K chunks

constexpr int A_BYTES   = TM * TK * 2;            // 16 KB
constexpr int B_BYTES   = TN * TK * 2;            // 16 KB
constexpr int STG_BYTES = A_BYTES + B_BYTES;      // 32 KB
constexpr int SMEM_BYTES = STAGES * STG_BYTES;    // 96 KB

constexpr int NTILE   = N_ROWS / TM;              // 64
constexpr int NTRI    = NTILE * (NTILE + 1) / 2;  // 2080 upper-tri tiles
constexpr int NSTRIPE = N_ROWS / 32;              // 256 scratch slots per row
constexpr int NRL_CTAS = N_ROWS / 32;             // 256 rowloss CTAs
constexpr int NPERS   = 296;                      // persistent CTAs (148 SMs x occ 2)

// ------------------------------------------------------------------
// Device scratch (static globals: allocation-free)
// Slot coverage per row (tr = row's tile): dir-1 writes tn*4+{0..3} for tn>=tr;
// dir-2 writes tm*4+{0,2} (values) and tm*4+{1,3} (zeros) for tm<tr
// -> every slot written exactly once; no zero-fill kernel.
// ------------------------------------------------------------------
__device__ __nv_bfloat16 g_x[(size_t)N_ROWS * DIM];   // normalized * sqrt(5)
__device__ float g_ps[NSTRIPE * N_ROWS];              // partial sum exp(sim)
__device__ float g_pa[NSTRIPE * N_ROWS];              // partial sum lbl*sim
__device__ float g_pb[NSTRIPE * N_ROWS];              // partial sum lbl
__device__ float g_blocksum[NRL_CTAS];                // per-rowloss-CTA loss partials

// ------------------------------------------------------------------
// PTX helpers
// ------------------------------------------------------------------
__device__ __forceinline__ uint32_t smem_u32(const void* p) {
    uint32_t a;
    asm("{ .reg .u64 t; cvta.to.shared.u64 t, %1; cvt.u32.u64 %0, t; }" : "=r"(a) : "l"(p));
    return a;
}

__device__ __forceinline__ void cp_async16(uint32_t dst, const void* src) {
    asm volatile("{ .reg .u64 g; cvta.to.global.u64 g, %1; "
                 "cp.async.cg.shared.global [%0], [g], 16; }"
                 :: "r"(dst), "l"(src) : "memory");
}
#define CP_COMMIT() asm volatile("cp.async.commit_group;" ::: "memory")
#define CP_WAIT(N)  asm volatile("cp.async.wait_group %0;" :: "n"(N) : "memory")

#define LDSM_X4(R0, R1, R2, R3, ADDR) \
    asm volatile("ldmatrix.sync.aligned.m8n8.x4.shared.b16 {%0,%1,%2,%3}, [%4];" \
                 : "=r"(R0), "=r"(R1), "=r"(R2), "=r"(R3) : "r"(ADDR))

__device__ __forceinline__ void mma_bf16(float* d, const uint32_t* a, const uint32_t* b) {
    asm volatile(
        "mma.sync.aligned.m16n8k16.row.col.f32.bf16.bf16.f32 "
        "{%0,%1,%2,%3}, {%4,%5,%6,%7}, {%8,%9}, {%0,%1,%2,%3};"
        : "+f"(d[0]), "+f"(d[1]), "+f"(d[2]), "+f"(d[3])
        : "r"(a[0]), "r"(a[1]), "r"(a[2]), "r"(a[3]), "r"(b[0]), "r"(b[1]));
}

// ------------------------------------------------------------------
// Kernel 1: row-normalize, fold sqrt(1/T), cast to bf16
// ------------------------------------------------------------------
__global__ __launch_bounds__(256) void coref_norm_kernel(const float* __restrict__ e) {
    const int row = blockIdx.x, t = threadIdx.x;
    const float* r = e + (size_t)row * DIM;
    float x0 = r[t], x1 = r[t + 256], x2 = r[t + 512], x3 = r[t + 768];
    float ss = x0 * x0 + x1 * x1 + x2 * x2 + x3 * x3;
    #pragma unroll
    for (int o = 16; o > 0; o >>= 1) ss += __shfl_xor_sync(0xffffffffu, ss, o);
    __shared__ float ws[8];
    if ((t & 31) == 0) ws[t >> 5] = ss;
    __syncthreads();
    float tot = ws[0] + ws[1] + ws[2] + ws[3] + ws[4] + ws[5] + ws[6] + ws[7];
    float scale = SQRT_INV_TEMP / fmaxf(sqrtf(tot), 1e-8f);
    __nv_bfloat16* op = g_x + (size_t)row * DIM;
    op[t]       = __float2bfloat16(x0 * scale);
    op[t + 256] = __float2bfloat16(x1 * scale);
    op[t + 512] = __float2bfloat16(x2 * scale);
    op[t + 768] = __float2bfloat16(x3 * scale);
}

// ------------------------------------------------------------------
// Kernel 2: persistent fused upper-triangular tile GEMM (mma.sync bf16)
//           + two-direction softmax/label epilogue (sim is symmetric)
// (GEMM inner body identical to the 232.2us R9 version — register-critical)
// ------------------------------------------------------------------
__device__ __forceinline__ void load_stage(uint32_t sbuf, int row_a, int row_b,
                                           int kc, int tid) {
    const __nv_bfloat16* gA = g_x + (size_t)row_a * DIM + kc * TK;
    #pragma unroll
    for (int i = 0; i < 4; ++i) {                 // A: 128 rows x 8 chunks (16B)
        int id = tid + (i << 8);
        int r = id >> 3, c = id & 7;
        uint32_t sw = (uint32_t)(r * 128) + (uint32_t)((c ^ (r & 7)) << 4);
        cp_async16(sbuf + sw, gA + (size_t)r * DIM + c * 8);
    }
    const __nv_bfloat16* gB = g_x + (size_t)row_b * DIM + kc * TK;
    uint32_t bb = sbuf + A_BYTES;
    #pragma unroll
    for (int i = 0; i < 4; ++i) {                 // B: 128 rows x 8 chunks
        int id = tid + (i << 8);
        int r = id >> 3, c = id & 7;
        uint32_t sw = (uint32_t)(r * 128) + (uint32_t)((c ^ (r & 7)) << 4);
        cp_async16(bb + sw, gB + (size_t)r * DIM + c * 8);
    }
}

__global__ __launch_bounds__(THREADS, 2)
void coref_main_kernel(const float* __restrict__ labels) {
    extern __shared__ char smem_raw[];
    const uint32_t sb = smem_u32(smem_raw);

    const int tid  = threadIdx.x;
    const int lane = tid & 31;
    const int warp = tid >> 5;
    const int warp_m = warp & 1;        // 0..1 -> 64-row half
    const int warp_n = warp >> 1;       // 0..3 -> 32-col stripe

    // ldmatrix lane addressing (tile-independent)
    const int a_row_in = (lane & 7) + ((lane >> 3) & 1) * 8;
    const int a_hi     = lane >> 4;
    const int b_row_in = (lane & 7) + (lane >> 4) * 8;
    const int b_hi     = (lane >> 3) & 1;

    int a_rowbyte[4], a_rx[4];
    #pragma unroll
    for (int mi = 0; mi < 4; ++mi) {
        int r = warp_m * 64 + mi * 16 + a_row_in;
        a_rowbyte[mi] = r * 128;
        a_rx[mi] = r & 7;
    }
    int b_rowbyte[2], b_rx[2];
    #pragma unroll
    for (int g = 0; g < 2; ++g) {
        int r = warp_n * 32 + g * 16 + b_row_in;
        b_rowbyte[g] = r * 128;
        b_rx[g] = r & 7;
    }

    const int qrow = lane >> 2;        // 0..7
    const int qcol = (lane & 3) * 2;   // 0,2,4,6

    for (int tile = blockIdx.x; tile < NTRI; tile += NPERS) {
        // Decode tile -> upper-triangular (tm, tn), tm <= tn
        int brem = tile, tm = 0;
        while (brem >= NTILE - tm) { brem -= NTILE - tm; ++tm; }
        const int tn = tm + brem;
        const int row0 = tm * TM;
        const int col0 = tn * TN;
        const bool offdiag = (tm != tn);

        // Hazard fence: previous tile's kc=15 LDSM reads of stage 0 must drain
        // before this tile's prologue cp.async overwrites it.
        __syncthreads();

        // Prologue: prefetch stages 0,1
        load_stage(sb,              row0, col0, 0, tid); CP_COMMIT();
        load_stage(sb + STG_BYTES,  row0, col0, 1, tid); CP_COMMIT();

        float acc[4][4][4];                          // [mi][ni][frag]
        #pragma unroll
        for (int mi = 0; mi < 4; ++mi)
            #pragma unroll
            for (int ni = 0; ni < 4; ++ni)
                #pragma unroll
                for (int j = 0; j < 4; ++j) acc[mi][ni][j] = 0.f;

        for (int kc = 0; kc < NKC; ++kc) {
            if (kc == NKC - 1) { CP_WAIT(0); } else { CP_WAIT(1); }
            __syncthreads();

            if (kc + 2 < NKC) {
                load_stage(sb + ((kc + 2) % STAGES) * STG_BYTES, row0, col0, kc + 2, tid);
                CP_COMMIT();
            }

            const uint32_t sA = sb + (kc % STAGES) * STG_BYTES;
            const uint32_t sB = sA + A_BYTES;

            #pragma unroll
            for (int kk = 0; kk < 4; ++kk) {
                const int kk2 = kk * 2;
                uint32_t Af[4][4], Bf[4][2];
                #pragma unroll
                for (int mi = 0; mi < 4; ++mi) {
                    uint32_t addr = sA + a_rowbyte[mi]
                                  + (uint32_t)(((kk2 + a_hi) ^ a_rx[mi]) << 4);
                    LDSM_X4(Af[mi][0], Af[mi][1], Af[mi][2], Af[mi][3], addr);
                }
                #pragma unroll
                for (int g = 0; g < 2; ++g) {
                    uint32_t q0, q1, q2, q3;
                    uint32_t addr = sB + b_rowbyte[g]
                                  + (uint32_t)(((kk2 + b_hi) ^ b_rx[g]) << 4);
                    LDSM_X4(q0, q1, q2, q3, addr);
                    Bf[g * 2 + 0][0] = q0; Bf[g * 2 + 0][1] = q1;
                    Bf[g * 2 + 1][0] = q2; Bf[g * 2 + 1][1] = q3;
                }
                #pragma unroll
                for (int mi = 0; mi < 4; ++mi)
                    #pragma unroll
                    for (int ni = 0; ni < 4; ++ni)
                        mma_bf16(acc[mi][ni], Af[mi], Bf[ni]);
            }
        }

        // ---------------- epilogue ----------------
        // ---- pass 1: row partials for m-block rows (dir-1) ----
        {
            const int stripe = tn * 4 + warp_n;
            #pragma unroll
            for (int mi = 0; mi < 4; ++mi) {
                #pragma unroll
                for (int h = 0; h < 2; ++h) {
                    const int grow = row0 + warp_m * 64 + mi * 16 + qrow + h * 8;
                    const float* lrow = labels + (size_t)grow * N_ROWS + col0 + warp_n * 32;
                    float s = 0.f, a = 0.f, b = 0.f;
                    #pragma unroll
                    for (int ni = 0; ni < 4; ++ni) {
                        const int gcol = col0 + warp_n * 32 + ni * 8 + qcol;
                        float2 lv = __ldcs((const float2*)(lrow + ni * 8 + qcol));
                        float s0 = acc[mi][ni][h * 2 + 0];
                        float s1 = acc[mi][ni][h * 2 + 1];
                        if (gcol != grow) {                  // only binds on diag tiles
                            s += __expf(s0);
                            a = fmaf(lv.x, s0, a);
                            b += lv.x;
                        }
                        if (gcol + 1 != grow) {
                            s += __expf(s1);
                            a = fmaf(lv.y, s1, a);
                            b += lv.y;
                        }
                    }
                    s += __shfl_xor_sync(0xffffffffu, s, 1);
                    s += __shfl_xor_sync(0xffffffffu, s, 2);
                    a += __shfl_xor_sync(0xffffffffu, a, 1);
                    a += __shfl_xor_sync(0xffffffffu, a, 2);
                    b += __shfl_xor_sync(0xffffffffu, b, 1);
                    b += __shfl_xor_sync(0xffffffffu, b, 2);
                    if ((lane & 3) == 0) {
                        g_ps[stripe * N_ROWS + grow] = s;
                        g_pa[stripe * N_ROWS + grow] = a;
                        g_pb[stripe * N_ROWS + grow] = b;
                    }
                }
            }
        }

        // ---- pass 2 (off-diag only): column partials for n-block rows (dir-2) ----
        if (offdiag) {
            const int slot  = tm * 4 + warp_m * 2;
            const int zslot = slot + 1;                 // hole slot: zero-filled here
            #pragma unroll
            for (int ni = 0; ni < 4; ++ni) {
                const int gc0 = col0 + warp_n * 32 + ni * 8 + qcol;   // out rows gc0, gc0+1
                const float* lc0 = labels + (size_t)gc0 * N_ROWS;
                const float* lc1 = lc0 + N_ROWS;
                float s0 = 0.f, s1 = 0.f, a0 = 0.f, a1 = 0.f, b0 = 0.f, b1 = 0.f;
                #pragma unroll
                for (int mi = 0; mi < 4; ++mi) {
                    #pragma unroll
                    for (int h = 0; h < 2; ++h) {
                        const int grow = row0 + warp_m * 64 + mi * 16 + h * 8 + qrow;
                        float v0 = acc[mi][ni][h * 2 + 0];
                        float v1 = acc[mi][ni][h * 2 + 1];
                        float l0 = __ldcs(lc0 + grow);     // lbl[gc0][grow]
                        float l1 = __ldcs(lc1 + grow);     // lbl[gc0+1][grow]
                        s0 += __expf(v0);
                        s1 += __expf(v1);
                        a0 = fmaf(l0, v0, a0);
                        a1 = fmaf(l1, v1, a1);
                        b0 += l0;
                        b1 += l1;
                    }
                }
                #pragma unroll
                for (int o = 4; o <= 16; o <<= 1) {
                    s0 += __shfl_xor_sync(0xffffffffu, s0, o);
                    s1 += __shfl_xor_sync(0xffffffffu, s1, o);
                    a0 += __shfl_xor_sync(0xffffffffu, a0, o);
                    a1 += __shfl_xor_sync(0xffffffffu, a1, o);
                    b0 += __shfl_xor_sync(0xffffffffu, b0, o);
                    b1 += __shfl_xor_sync(0xffffffffu, b1, o);
                }
                if (qrow == 0) {
                    g_ps[slot * N_ROWS + gc0]     = s0;
                    g_ps[slot * N_ROWS + gc0 + 1] = s1;
                    g_pa[slot * N_ROWS + gc0]     = a0;
                    g_pa[slot * N_ROWS + gc0 + 1] = a1;
                    g_pb[slot * N_ROWS + gc0]     = b0;
                    g_pb[slot * N_ROWS + gc0 + 1] = b1;
                    // zero-fill the hole slot (replaces a standalone zero kernel)
                    g_ps[zslot * N_ROWS + gc0]     = 0.f;
                    g_ps[zslot * N_ROWS + gc0 + 1] = 0.f;
                    g_pa[zslot * N_ROWS + gc0]     = 0.f;
                    g_pa[zslot * N_ROWS + gc0 + 1] = 0.f;
                    g_pb[zslot * N_ROWS + gc0]     = 0.f;
                    g_pb[zslot * N_ROWS + gc0 + 1] = 0.f;
                }
            }
        }
    }
}

// ------------------------------------------------------------------
// Kernel 3: per-row reduction of the 256 stripe partials + per-CTA loss partial
// ------------------------------------------------------------------
__global__ __launch_bounds__(256) void coref_rowloss_kernel() {
    const int rlane = threadIdx.x & 31;
    const int grp   = threadIdx.x >> 5;            // 0..7
    const int row   = blockIdx.x * 32 + rlane;
    float S = 0.f, A = 0.f, B = 0.f;
    #pragma unroll 8
    for (int k = 0; k < 32; ++k) {
        const int t = grp * 32 + k;
        S += g_ps[t * N_ROWS + row];
        A += g_pa[t * N_ROWS + row];
        B += g_pb[t * N_ROWS + row];
    }
    __shared__ float ss[8][32], sa[8][32], sb2[8][32];
    ss[grp][rlane] = S; sa[grp][rlane] = A; sb2[grp][rlane] = B;
    __syncthreads();
    if (grp == 0) {
        float St = 0.f, At = 0.f, Bt = 0.f;
        #pragma unroll
        for (int g = 0; g < 8; ++g) {
            St += ss[g][rlane]; At += sa[g][rlane]; Bt += sb2[g][rlane];
        }
        // loss_i = lse_i * B_i - A_i   (no max shift: |sim| <= 5)
        float loss = logf(St) * Bt - At;
        #pragma unroll
        for (int o = 16; o > 0; o >>= 1) loss += __shfl_xor_sync(0xffffffffu, loss, o);
        if (rlane == 0) g_blocksum[blockIdx.x] = loss;
    }
}

// ------------------------------------------------------------------
// Kernel 4: deterministic fixed-tree reduce of 256 block partials -> mean
// ------------------------------------------------------------------
__global__ __launch_bounds__(256) void coref_final_kernel(float* __restrict__ out) {
    __shared__ float sm[256];
    const int t = threadIdx.x;
    sm[t] = g_blocksum[t];
    __syncthreads();
    #pragma unroll
    for (int s = 128; s > 0; s >>= 1) {
        if (t < s) sm[t] += sm[t + s];
        __syncthreads();
    }
    if (t == 0) out[0] = sm[0] * (1.0f / (float)N_ROWS);
}

// ------------------------------------------------------------------
// Launcher (graph-capturable)
// ------------------------------------------------------------------
extern "C" void kernel_launch(void* const* d_in, const int* in_sizes, int n_in,
                              void* d_out, int out_size) {
    const float* embs   = (const float*)d_in[0];
    const float* labels = (const float*)d_in[1];
    if (n_in >= 2 && in_sizes[0] == N_ROWS * N_ROWS) {  // defensive input-order check
        const float* tmp = embs; embs = labels; labels = tmp;
    }
    float* out = (float*)d_out;

    cudaFuncSetAttribute(coref_main_kernel,
                         cudaFuncAttributeMaxDynamicSharedMemorySize, SMEM_BYTES);

    coref_norm_kernel<<<N_ROWS, 256>>>(embs);
    coref_main_kernel<<<NPERS, THREADS, SMEM_BYTES>>>(labels);
    coref_rowloss_kernel<<<NRL_CTAS, 256>>>();
    coref_final_kernel<<<1, 256>>>(out);
}

// round 12
// speedup vs baseline: 2.1447x; 1.0985x over previous
#include <cuda_runtime.h>
#include <cuda_bf16.h>
#include <cstdint>

// ------------------------------------------------------------------
// Problem constants
// ------------------------------------------------------------------
constexpr int N_ROWS = 8192;
constexpr int DIM    = 1024;
constexpr float SQRT_INV_TEMP = 2.23606797749978969f;   // sqrt(1/0.2)

constexpr int TM = 128;               // CTA tile rows
constexpr int TN = 128;               // CTA tile cols
constexpr int TK = 64;                // bf16 K elems per stage (128 B rows)
constexpr int STAGES  = 3;
constexpr int THREADS = 256;          // 8 warps, 2 (M) x 4 (N)
constexpr int NKC = DIM / TK;         // 16 K chunks

constexpr int A_BYTES   = TM * TK * 2;            // 16 KB
constexpr int B_BYTES   = TN * TK * 2;            // 16 KB
constexpr int STG_BYTES = A_BYTES + B_BYTES;      // 32 KB
constexpr int SMEM_BYTES = STAGES * STG_BYTES;    // 96 KB

constexpr int NTILE   = N_ROWS / TM;              // 64
constexpr int NTRI    = NTILE * (NTILE + 1) / 2;  // 2080 upper-tri tiles
constexpr int NOFFD   = NTRI - NTILE;             // 2016 off-diagonal tiles
constexpr int NSTRIPE = N_ROWS / 32;              // 256 scratch slots per row
constexpr int NRL_CTAS = N_ROWS / 32;             // 256 rowloss CTAs

// ------------------------------------------------------------------
// Device scratch (static globals: allocation-free)
// Slot coverage per row (tr = row's tile): dir-1 writes tn*4+{0..3} for tn>=tr;
// dir-2 writes tm*4+{0,2} (values) and tm*4+{1,3} (zeros) for tm<tr
// -> every slot written exactly once; no zero-fill kernel.
// ------------------------------------------------------------------
__device__ __nv_bfloat16 g_x[(size_t)N_ROWS * DIM];   // normalized * sqrt(5)
__device__ float g_ps[NSTRIPE * N_ROWS];              // partial sum exp(sim)
__device__ float g_pa[NSTRIPE * N_ROWS];              // partial sum lbl*sim
__device__ float g_pb[NSTRIPE * N_ROWS];              // partial sum lbl
__device__ float g_blocksum[NRL_CTAS];                // per-rowloss-CTA loss partials
__device__ unsigned g_done;                           // rowloss completion counter
                                                      // (zero-init; last block resets)

// ------------------------------------------------------------------
// PTX helpers
// ------------------------------------------------------------------
__device__ __forceinline__ uint32_t smem_u32(const void* p) {
    uint32_t a;
    asm("{ .reg .u64 t; cvta.to.shared.u64 t, %1; cvt.u32.u64 %0, t; }" : "=r"(a) : "l"(p));
    return a;
}

__device__ __forceinline__ void cp_async16(uint32_t dst, const void* src) {
    asm volatile("{ .reg .u64 g; cvta.to.global.u64 g, %1; "
                 "cp.async.cg.shared.global [%0], [g], 16; }"
                 :: "r"(dst), "l"(src) : "memory");
}
#define CP_COMMIT() asm volatile("cp.async.commit_group;" ::: "memory")
#define CP_WAIT(N)  asm volatile("cp.async.wait_group %0;" :: "n"(N) : "memory")

#define LDSM_X4(R0, R1, R2, R3, ADDR) \
    asm volatile("ldmatrix.sync.aligned.m8n8.x4.shared.b16 {%0,%1,%2,%3}, [%4];" \
                 : "=r"(R0), "=r"(R1), "=r"(R2), "=r"(R3) : "r"(ADDR))

__device__ __forceinline__ void mma_bf16(float* d, const uint32_t* a, const uint32_t* b) {
    asm volatile(
        "mma.sync.aligned.m16n8k16.row.col.f32.bf16.bf16.f32 "
        "{%0,%1,%2,%3}, {%4,%5,%6,%7}, {%8,%9}, {%0,%1,%2,%3};"
        : "+f"(d[0]), "+f"(d[1]), "+f"(d[2]), "+f"(d[3])
        : "r"(a[0]), "r"(a[1]), "r"(a[2]), "r"(a[3]), "r"(b[0]), "r"(b[1]));
}

// ------------------------------------------------------------------
// Kernel 1: row-normalize, fold sqrt(1/T), cast to bf16
// ------------------------------------------------------------------
__global__ __launch_bounds__(256) void coref_norm_kernel(const float* __restrict__ e) {
    const int row = blockIdx.x, t = threadIdx.x;
    const float* r = e + (size_t)row * DIM;
    float x0 = r[t], x1 = r[t + 256], x2 = r[t + 512], x3 = r[t + 768];
    float ss = x0 * x0 + x1 * x1 + x2 * x2 + x3 * x3;
    #pragma unroll
    for (int o = 16; o > 0; o >>= 1) ss += __shfl_xor_sync(0xffffffffu, ss, o);
    __shared__ float ws[8];
    if ((t & 31) == 0) ws[t >> 5] = ss;
    __syncthreads();
    float tot = ws[0] + ws[1] + ws[2] + ws[3] + ws[4] + ws[5] + ws[6] + ws[7];
    float scale = SQRT_INV_TEMP / fmaxf(sqrtf(tot), 1e-8f);
    __nv_bfloat16* op = g_x + (size_t)row * DIM;
    op[t]       = __float2bfloat16(x0 * scale);
    op[t + 256] = __float2bfloat16(x1 * scale);
    op[t + 512] = __float2bfloat16(x2 * scale);
    op[t + 768] = __float2bfloat16(x3 * scale);
}

// ------------------------------------------------------------------
// Kernel 2: fused upper-triangular tile GEMM (mma.sync bf16)
//           + two-direction softmax/label epilogue (sim is symmetric)
// (GEMM body identical to the 232.2us R9 version — register-critical.
//  Only change: bid->tile remap puts the 64 diagonal tiles LAST so the
//  tail wave runs the cheapest tiles.)
// ------------------------------------------------------------------
__device__ __forceinline__ void load_stage(uint32_t sbuf, int row_a, int row_b,
                                           int kc, int tid) {
    const __nv_bfloat16* gA = g_x + (size_t)row_a * DIM + kc * TK;
    #pragma unroll
    for (int i = 0; i < 4; ++i) {                 // A: 128 rows x 8 chunks (16B)
        int id = tid + (i << 8);
        int r = id >> 3, c = id & 7;
        uint32_t sw = (uint32_t)(r * 128) + (uint32_t)((c ^ (r & 7)) << 4);
        cp_async16(sbuf + sw, gA + (size_t)r * DIM + c * 8);
    }
    const __nv_bfloat16* gB = g_x + (size_t)row_b * DIM + kc * TK;
    uint32_t bb = sbuf + A_BYTES;
    #pragma unroll
    for (int i = 0; i < 4; ++i) {                 // B: 128 rows x 8 chunks
        int id = tid + (i << 8);
        int r = id >> 3, c = id & 7;
        uint32_t sw = (uint32_t)(r * 128) + (uint32_t)((c ^ (r & 7)) << 4);
        cp_async16(bb + sw, gB + (size_t)r * DIM + c * 8);
    }
}

__global__ __launch_bounds__(THREADS, 2)
void coref_main_kernel(const float* __restrict__ labels) {
    extern __shared__ char smem_raw[];
    const uint32_t sb = smem_u32(smem_raw);

    const int tid  = threadIdx.x;
    const int lane = tid & 31;
    const int warp = tid >> 5;
    const int warp_m = warp & 1;        // 0..1 -> 64-row half
    const int warp_n = warp >> 1;       // 0..3 -> 32-col stripe

    // Decode blockIdx.x: bids [0, NOFFD) -> off-diagonal tiles (tm < tn),
    // bids [NOFFD, NTRI) -> diagonal tiles (launched/finishing last).
    int tm, tn;
    {
        int brem = blockIdx.x;
        if (brem < NOFFD) {
            tm = 0;
            while (brem >= NTILE - 1 - tm) { brem -= NTILE - 1 - tm; ++tm; }
            tn = tm + 1 + brem;
        } else {
            tm = tn = brem - NOFFD;
        }
    }
    const int row0 = tm * TM;
    const int col0 = tn * TN;
    const bool offdiag = (tm != tn);

    // Prologue: prefetch stages 0,1
    load_stage(sb,              row0, col0, 0, tid); CP_COMMIT();
    load_stage(sb + STG_BYTES,  row0, col0, 1, tid); CP_COMMIT();

    float acc[4][4][4];                          // [mi][ni][frag]
    #pragma unroll
    for (int mi = 0; mi < 4; ++mi)
        #pragma unroll
        for (int ni = 0; ni < 4; ++ni)
            #pragma unroll
            for (int j = 0; j < 4; ++j) acc[mi][ni][j] = 0.f;

    // ldmatrix lane addressing
    const int a_row_in = (lane & 7) + ((lane >> 3) & 1) * 8;
    const int a_hi     = lane >> 4;
    const int b_row_in = (lane & 7) + (lane >> 4) * 8;
    const int b_hi     = (lane >> 3) & 1;

    int a_rowbyte[4], a_rx[4];
    #pragma unroll
    for (int mi = 0; mi < 4; ++mi) {
        int r = warp_m * 64 + mi * 16 + a_row_in;
        a_rowbyte[mi] = r * 128;
        a_rx[mi] = r & 7;
    }
    int b_rowbyte[2], b_rx[2];
    #pragma unroll
    for (int g = 0; g < 2; ++g) {
        int r = warp_n * 32 + g * 16 + b_row_in;
        b_rowbyte[g] = r * 128;
        b_rx[g] = r & 7;
    }

    for (int kc = 0; kc < NKC; ++kc) {
        if (kc == NKC - 1) { CP_WAIT(0); } else { CP_WAIT(1); }
        __syncthreads();

        if (kc + 2 < NKC) {
            load_stage(sb + ((kc + 2) % STAGES) * STG_BYTES, row0, col0, kc + 2, tid);
            CP_COMMIT();
        }

        const uint32_t sA = sb + (kc % STAGES) * STG_BYTES;
        const uint32_t sB = sA + A_BYTES;

        #pragma unroll
        for (int kk = 0; kk < 4; ++kk) {
            const int kk2 = kk * 2;
            uint32_t Af[4][4], Bf[4][2];
            #pragma unroll
            for (int mi = 0; mi < 4; ++mi) {
                uint32_t addr = sA + a_rowbyte[mi]
                              + (uint32_t)(((kk2 + a_hi) ^ a_rx[mi]) << 4);
                LDSM_X4(Af[mi][0], Af[mi][1], Af[mi][2], Af[mi][3], addr);
            }
            #pragma unroll
            for (int g = 0; g < 2; ++g) {
                uint32_t q0, q1, q2, q3;
                uint32_t addr = sB + b_rowbyte[g]
                              + (uint32_t)(((kk2 + b_hi) ^ b_rx[g]) << 4);
                LDSM_X4(q0, q1, q2, q3, addr);
                Bf[g * 2 + 0][0] = q0; Bf[g * 2 + 0][1] = q1;
                Bf[g * 2 + 1][0] = q2; Bf[g * 2 + 1][1] = q3;
            }
            #pragma unroll
            for (int mi = 0; mi < 4; ++mi)
                #pragma unroll
                for (int ni = 0; ni < 4; ++ni)
                    mma_bf16(acc[mi][ni], Af[mi], Bf[ni]);
        }
    }

    // ---------------- epilogue ----------------
    // Fragment: rows qrow, qrow+8; cols 2*(lane%4), +1
    const int qrow = lane >> 2;        // 0..7
    const int qcol = (lane & 3) * 2;   // 0,2,4,6

    // ---- pass 1: row partials for m-block rows (dir-1) ----
    {
        const int stripe = tn * 4 + warp_n;
        #pragma unroll
        for (int mi = 0; mi < 4; ++mi) {
            #pragma unroll
            for (int h = 0; h < 2; ++h) {
                const int grow = row0 + warp_m * 64 + mi * 16 + qrow + h * 8;
                const float* lrow = labels + (size_t)grow * N_ROWS + col0 + warp_n * 32;
                float s = 0.f, a = 0.f, b = 0.f;
                #pragma unroll
                for (int ni = 0; ni < 4; ++ni) {
                    const int gcol = col0 + warp_n * 32 + ni * 8 + qcol;
                    float2 lv = __ldcs((const float2*)(lrow + ni * 8 + qcol));
                    float s0 = acc[mi][ni][h * 2 + 0];
                    float s1 = acc[mi][ni][h * 2 + 1];
                    if (gcol != grow) {                  // only binds on diag tiles
                        s += __expf(s0);
                        a = fmaf(lv.x, s0, a);
                        b += lv.x;
                    }
                    if (gcol + 1 != grow) {
                        s += __expf(s1);
                        a = fmaf(lv.y, s1, a);
                        b += lv.y;
                    }
                }
                s += __shfl_xor_sync(0xffffffffu, s, 1);
                s += __shfl_xor_sync(0xffffffffu, s, 2);
                a += __shfl_xor_sync(0xffffffffu, a, 1);
                a += __shfl_xor_sync(0xffffffffu, a, 2);
                b += __shfl_xor_sync(0xffffffffu, b, 1);
                b += __shfl_xor_sync(0xffffffffu, b, 2);
                if ((lane & 3) == 0) {
                    g_ps[stripe * N_ROWS + grow] = s;
                    g_pa[stripe * N_ROWS + grow] = a;
                    g_pb[stripe * N_ROWS + grow] = b;
                }
            }
        }
    }

    // ---- pass 2 (off-diag only): column partials for n-block rows (dir-2) ----
    if (offdiag) {
        const int slot  = tm * 4 + warp_m * 2;
        const int zslot = slot + 1;                 // hole slot: zero-filled here
        #pragma unroll
        for (int ni = 0; ni < 4; ++ni) {
            const int gc0 = col0 + warp_n * 32 + ni * 8 + qcol;   // output rows gc0, gc0+1
            const float* lc0 = labels + (size_t)gc0 * N_ROWS;
            const float* lc1 = lc0 + N_ROWS;
            float s0 = 0.f, s1 = 0.f, a0 = 0.f, a1 = 0.f, b0 = 0.f, b1 = 0.f;
            #pragma unroll
            for (int mi = 0; mi < 4; ++mi) {
                #pragma unroll
                for (int h = 0; h < 2; ++h) {
                    const int grow = row0 + warp_m * 64 + mi * 16 + h * 8 + qrow;
                    float v0 = acc[mi][ni][h * 2 + 0];
                    float v1 = acc[mi][ni][h * 2 + 1];
                    float l0 = __ldcs(lc0 + grow);     // lbl[gc0][grow]
                    float l1 = __ldcs(lc1 + grow);     // lbl[gc0+1][grow]
                    s0 += __expf(v0);
                    s1 += __expf(v1);
                    a0 = fmaf(l0, v0, a0);
                    a1 = fmaf(l1, v1, a1);
                    b0 += l0;
                    b1 += l1;
                }
            }
            #pragma unroll
            for (int o = 4; o <= 16; o <<= 1) {
                s0 += __shfl_xor_sync(0xffffffffu, s0, o);
                s1 += __shfl_xor_sync(0xffffffffu, s1, o);
                a0 += __shfl_xor_sync(0xffffffffu, a0, o);
                a1 += __shfl_xor_sync(0xffffffffu, a1, o);
                b0 += __shfl_xor_sync(0xffffffffu, b0, o);
                b1 += __shfl_xor_sync(0xffffffffu, b1, o);
            }
            if (qrow == 0) {
                g_ps[slot * N_ROWS + gc0]     = s0;
                g_ps[slot * N_ROWS + gc0 + 1] = s1;
                g_pa[slot * N_ROWS + gc0]     = a0;
                g_pa[slot * N_ROWS + gc0 + 1] = a1;
                g_pb[slot * N_ROWS + gc0]     = b0;
                g_pb[slot * N_ROWS + gc0 + 1] = b1;
                // zero-fill the hole slot (replaces a standalone zero kernel)
                g_ps[zslot * N_ROWS + gc0]     = 0.f;
                g_ps[zslot * N_ROWS + gc0 + 1] = 0.f;
                g_pa[zslot * N_ROWS + gc0]     = 0.f;
                g_pa[zslot * N_ROWS + gc0 + 1] = 0.f;
                g_pb[zslot * N_ROWS + gc0]     = 0.f;
                g_pb[zslot * N_ROWS + gc0 + 1] = 0.f;
            }
        }
    }
}

// ------------------------------------------------------------------
// Kernel 3: per-row reduction of the 256 stripe partials + per-CTA loss
// partial + last-block final reduction (replaces the separate kernel 4).
// Deterministic: the final sum is a fixed tree over all 256 partials,
// independent of which block happens to run it.
// ------------------------------------------------------------------
__global__ __launch_bounds__(256) void coref_rowloss_kernel(float* __restrict__ out) {
    const int rlane = threadIdx.x & 31;
    const int grp   = threadIdx.x >> 5;            // 0..7
    const int row   = blockIdx.x * 32 + rlane;
    float S = 0.f, A = 0.f, B = 0.f;
    #pragma unroll 8
    for (int k = 0; k < 32; ++k) {
        const int t = grp * 32 + k;
        S += g_ps[t * N_ROWS + row];
        A += g_pa[t * N_ROWS + row];
        B += g_pb[t * N_ROWS + row];
    }
    __shared__ float ss[8][32], sa[8][32], sb2[8][32];
    ss[grp][rlane] = S; sa[grp][rlane] = A; sb2[grp][rlane] = B;
    __syncthreads();
    if (grp == 0) {
        float St = 0.f, At = 0.f, Bt = 0.f;
        #pragma unroll
        for (int g = 0; g < 8; ++g) {
            St += ss[g][rlane]; At += sa[g][rlane]; Bt += sb2[g][rlane];
        }
        // loss_i = lse_i * B_i - A_i   (no max shift: |sim| <= 5)
        float loss = logf(St) * Bt - At;
        #pragma unroll
        for (int o = 16; o > 0; o >>= 1) loss += __shfl_xor_sync(0xffffffffu, loss, o);

        unsigned last = 0;
        if (rlane == 0) {
            g_blocksum[blockIdx.x] = loss;
            __threadfence();                            // publish before counting
            unsigned old = atomicAdd(&g_done, 1u);
            last = (old == NRL_CTAS - 1) ? 1u : 0u;
        }
        last = __shfl_sync(0xffffffffu, last, 0);
        if (last) {
            __threadfence();                            // acquire all partials
            float v = 0.f;
            #pragma unroll
            for (int i = 0; i < NRL_CTAS / 32; ++i)     // fixed per-lane order
                v += g_blocksum[rlane + i * 32];
            #pragma unroll
            for (int o = 16; o > 0; o >>= 1) v += __shfl_xor_sync(0xffffffffu, v, o);
            if (rlane == 0) {
                out[0] = v * (1.0f / (float)N_ROWS);
                g_done = 0;                             // reset for next graph replay
            }
        }
    }
}

// ------------------------------------------------------------------
// Launcher (graph-capturable)
// ------------------------------------------------------------------
extern "C" void kernel_launch(void* const* d_in, const int* in_sizes, int n_in,
                              void* d_out, int out_size) {
    const float* embs   = (const float*)d_in[0];
    const float* labels = (const float*)d_in[1];
    if (n_in >= 2 && in_sizes[0] == N_ROWS * N_ROWS) {  // defensive input-order check
        const float* tmp = embs; embs = labels; labels = tmp;
    }
    float* out = (float*)d_out;

    cudaFuncSetAttribute(coref_main_kernel,
                         cudaFuncAttributeMaxDynamicSharedMemorySize, SMEM_BYTES);

    coref_norm_kernel<<<N_ROWS, 256>>>(embs);
    coref_main_kernel<<<NTRI, THREADS, SMEM_BYTES>>>(labels);
    coref_rowloss_kernel<<<NRL_CTAS, 256>>>(out);
}

// round 13
// speedup vs baseline: 2.1482x; 1.0016x over previous
#include <cuda_runtime.h>
#include <cuda_fp16.h>
#include <cstdint>

// ------------------------------------------------------------------
// Problem constants
// ------------------------------------------------------------------
constexpr int N_ROWS = 8192;
constexpr int DIM    = 1024;
constexpr float SQRT_INV_TEMP = 2.23606797749978969f;   // sqrt(1/0.2)

constexpr int TM = 128;               // CTA tile rows
constexpr int TN = 128;               // CTA tile cols
constexpr int TK = 64;                // fp16 K elems per stage (128 B rows)
constexpr int STAGES  = 3;
constexpr int THREADS = 256;          // 8 warps, 2 (M) x 4 (N)
constexpr int NKC = DIM / TK;         // 16 K chunks

constexpr int A_BYTES   = TM * TK * 2;            // 16 KB
constexpr int B_BYTES   = TN * TK * 2;            // 16 KB
constexpr int STG_BYTES = A_BYTES + B_BYTES;      // 32 KB
constexpr int SMEM_BYTES = STAGES * STG_BYTES;    // 96 KB

constexpr int NTILE   = N_ROWS / TM;              // 64
constexpr int NTRI    = NTILE * (NTILE + 1) / 2;  // 2080 upper-tri tiles
constexpr int NSTRIPE = N_ROWS / 32;              // 256 scratch slots per row
constexpr int NRL_CTAS = N_ROWS / 32;             // 256 rowloss CTAs

// ------------------------------------------------------------------
// Device scratch (static globals: allocation-free)
// Slot coverage per row (tr = row's tile): dir-1 writes tn*4+{0..3} for tn>=tr;
// dir-2 writes tm*4+{0,2} (values) and tm*4+{1,3} (zeros) for tm<tr
// -> every slot written exactly once; no zero-fill kernel.
// ------------------------------------------------------------------
__device__ __half g_x[(size_t)N_ROWS * DIM];          // normalized * sqrt(5), fp16
__device__ float g_ps[NSTRIPE * N_ROWS];              // partial sum exp(sim)
__device__ float g_pa[NSTRIPE * N_ROWS];              // partial sum lbl*sim
__device__ float g_pb[NSTRIPE * N_ROWS];              // partial sum lbl
__device__ float g_blocksum[NRL_CTAS];                // per-rowloss-CTA loss partials
__device__ unsigned g_done;                           // rowloss completion counter

// ------------------------------------------------------------------
// PTX helpers
// ------------------------------------------------------------------
__device__ __forceinline__ uint32_t smem_u32(const void* p) {
    uint32_t a;
    asm("{ .reg .u64 t; cvta.to.shared.u64 t, %1; cvt.u32.u64 %0, t; }" : "=r"(a) : "l"(p));
    return a;
}

__device__ __forceinline__ void cp_async16(uint32_t dst, const void* src) {
    asm volatile("{ .reg .u64 g; cvta.to.global.u64 g, %1; "
                 "cp.async.cg.shared.global [%0], [g], 16; }"
                 :: "r"(dst), "l"(src) : "memory");
}
#define CP_COMMIT() asm volatile("cp.async.commit_group;" ::: "memory")
#define CP_WAIT(N)  asm volatile("cp.async.wait_group %0;" :: "n"(N) : "memory")

#define LDSM_X4(R0, R1, R2, R3, ADDR) \
    asm volatile("ldmatrix.sync.aligned.m8n8.x4.shared.b16 {%0,%1,%2,%3}, [%4];" \
                 : "=r"(R0), "=r"(R1), "=r"(R2), "=r"(R3) : "r"(ADDR))

// fp16-accumulator HMMA: D(f16x2 x2) += A(16x16 f16) * B(8x16 f16)^T
// D reg h = (c0,c1) for row-group h (rows qrow / qrow+8), cols qcol, qcol+1.
__device__ __forceinline__ void mma_f16(uint32_t* d, const uint32_t* a, const uint32_t* b) {
    asm volatile(
        "mma.sync.aligned.m16n8k16.row.col.f16.f16.f16.f16 "
        "{%0,%1}, {%2,%3,%4,%5}, {%6,%7}, {%0,%1};"
        : "+r"(d[0]), "+r"(d[1])
        : "r"(a[0]), "r"(a[1]), "r"(a[2]), "r"(a[3]), "r"(b[0]), "r"(b[1]));
}

// ------------------------------------------------------------------
// Kernel 1: row-normalize, fold sqrt(1/T), cast to fp16 (float4 loads)
// ------------------------------------------------------------------
__global__ __launch_bounds__(256) void coref_norm_kernel(const float* __restrict__ e) {
    const int row = blockIdx.x, t = threadIdx.x;
    const float4 v = ((const float4*)(e + (size_t)row * DIM))[t];
    float ss = v.x * v.x + v.y * v.y + v.z * v.z + v.w * v.w;
    #pragma unroll
    for (int o = 16; o > 0; o >>= 1) ss += __shfl_xor_sync(0xffffffffu, ss, o);
    __shared__ float ws[8];
    if ((t & 31) == 0) ws[t >> 5] = ss;
    __syncthreads();
    float tot = ws[0] + ws[1] + ws[2] + ws[3] + ws[4] + ws[5] + ws[6] + ws[7];
    float scale = SQRT_INV_TEMP / fmaxf(sqrtf(tot), 1e-8f);
    __half2 h01 = __floats2half2_rn(v.x * scale, v.y * scale);
    __half2 h23 = __floats2half2_rn(v.z * scale, v.w * scale);
    uint2 w;
    w.x = *(const unsigned*)&h01;
    w.y = *(const unsigned*)&h23;
    ((uint2*)(g_x + (size_t)row * DIM))[t] = w;
}

// ------------------------------------------------------------------
// Kernel 2: fused upper-triangular tile GEMM (mma.sync f16 accum)
//           + two-direction softmax/label epilogue (sim is symmetric)
// ------------------------------------------------------------------
__device__ __forceinline__ void load_stage(uint32_t sbuf, int row_a, int row_b,
                                           int kc, int tid) {
    const __half* gA = g_x + (size_t)row_a * DIM + kc * TK;
    #pragma unroll
    for (int i = 0; i < 4; ++i) {                 // A: 128 rows x 8 chunks (16B)
        int id = tid + (i << 8);
        int r = id >> 3, c = id & 7;
        uint32_t sw = (uint32_t)(r * 128) + (uint32_t)((c ^ (r & 7)) << 4);
        cp_async16(sbuf + sw, gA + (size_t)r * DIM + c * 8);
    }
    const __half* gB = g_x + (size_t)row_b * DIM + kc * TK;
    uint32_t bb = sbuf + A_BYTES;
    #pragma unroll
    for (int i = 0; i < 4; ++i) {                 // B: 128 rows x 8 chunks
        int id = tid + (i << 8);
        int r = id >> 3, c = id & 7;
        uint32_t sw = (uint32_t)(r * 128) + (uint32_t)((c ^ (r & 7)) << 4);
        cp_async16(bb + sw, gB + (size_t)r * DIM + c * 8);
    }
}

__global__ __launch_bounds__(THREADS, 2)
void coref_main_kernel(const float* __restrict__ labels) {
    extern __shared__ char smem_raw[];
    const uint32_t sb = smem_u32(smem_raw);

    const int tid  = threadIdx.x;
    const int lane = tid & 31;
    const int warp = tid >> 5;
    const int warp_m = warp & 1;        // 0..1 -> 64-row half
    const int warp_n = warp >> 1;       // 0..3 -> 32-col stripe

    // Decode blockIdx.x -> upper-triangular (tm, tn), tm <= tn  (R9 ordering)
    int brem = blockIdx.x, tm = 0;
    while (brem >= NTILE - tm) { brem -= NTILE - tm; ++tm; }
    const int tn = tm + brem;
    const int row0 = tm * TM;
    const int col0 = tn * TN;
    const bool offdiag = (tm != tn);

    // Prologue: prefetch stages 0,1
    load_stage(sb,              row0, col0, 0, tid); CP_COMMIT();
    load_stage(sb + STG_BYTES,  row0, col0, 1, tid); CP_COMMIT();

    uint32_t acc[4][4][2];                       // [mi][ni][rowgroup] f16x2 accum
    #pragma unroll
    for (int mi = 0; mi < 4; ++mi)
        #pragma unroll
        for (int ni = 0; ni < 4; ++ni) {
            acc[mi][ni][0] = 0u;                 // +0.0h x2
            acc[mi][ni][1] = 0u;
        }

    // ldmatrix lane addressing
    const int a_row_in = (lane & 7) + ((lane >> 3) & 1) * 8;
    const int a_hi     = lane >> 4;
    const int b_row_in = (lane & 7) + (lane >> 4) * 8;
    const int b_hi     = (lane >> 3) & 1;

    int a_rowbyte[4], a_rx[4];
    #pragma unroll
    for (int mi = 0; mi < 4; ++mi) {
        int r = warp_m * 64 + mi * 16 + a_row_in;
        a_rowbyte[mi] = r * 128;
        a_rx[mi] = r & 7;
    }
    int b_rowbyte[2], b_rx[2];
    #pragma unroll
    for (int g = 0; g < 2; ++g) {
        int r = warp_n * 32 + g * 16 + b_row_in;
        b_rowbyte[g] = r * 128;
        b_rx[g] = r & 7;
    }

    for (int kc = 0; kc < NKC; ++kc) {
        if (kc == NKC - 1) { CP_WAIT(0); } else { CP_WAIT(1); }
        __syncthreads();

        if (kc + 2 < NKC) {
            load_stage(sb + ((kc + 2) % STAGES) * STG_BYTES, row0, col0, kc + 2, tid);
            CP_COMMIT();
        }

        const uint32_t sA = sb + (kc % STAGES) * STG_BYTES;
        const uint32_t sB = sA + A_BYTES;

        #pragma unroll
        for (int kk = 0; kk < 4; ++kk) {
            const int kk2 = kk * 2;
            uint32_t Af[4][4], Bf[4][2];
            #pragma unroll
            for (int mi = 0; mi < 4; ++mi) {
                uint32_t addr = sA + a_rowbyte[mi]
                              + (uint32_t)(((kk2 + a_hi) ^ a_rx[mi]) << 4);
                LDSM_X4(Af[mi][0], Af[mi][1], Af[mi][2], Af[mi][3], addr);
            }
            #pragma unroll
            for (int g = 0; g < 2; ++g) {
                uint32_t q0, q1, q2, q3;
                uint32_t addr = sB + b_rowbyte[g]
                              + (uint32_t)(((kk2 + b_hi) ^ b_rx[g]) << 4);
                LDSM_X4(q0, q1, q2, q3, addr);
                Bf[g * 2 + 0][0] = q0; Bf[g * 2 + 0][1] = q1;
                Bf[g * 2 + 1][0] = q2; Bf[g * 2 + 1][1] = q3;
            }
            #pragma unroll
            for (int mi = 0; mi < 4; ++mi)
                #pragma unroll
                for (int ni = 0; ni < 4; ++ni)
                    mma_f16(acc[mi][ni], Af[mi], Bf[ni]);
        }
    }

    // ---------------- epilogue ----------------
    // f16 fragment: reg h = (cols qcol, qcol+1) of row (qrow + 8h)
    const int qrow = lane >> 2;        // 0..7
    const int qcol = (lane & 3) * 2;   // 0,2,4,6

    // ---- pass 1: row partials for m-block rows (dir-1) ----
    {
        const int stripe = tn * 4 + warp_n;
        #pragma unroll
        for (int mi = 0; mi < 4; ++mi) {
            #pragma unroll
            for (int h = 0; h < 2; ++h) {
                const int grow = row0 + warp_m * 64 + mi * 16 + qrow + h * 8;
                const float* lrow = labels + (size_t)grow * N_ROWS + col0 + warp_n * 32;
                float s = 0.f, a = 0.f, b = 0.f;
                #pragma unroll
                for (int ni = 0; ni < 4; ++ni) {
                    const int gcol = col0 + warp_n * 32 + ni * 8 + qcol;
                    float2 lv = __ldcs((const float2*)(lrow + ni * 8 + qcol));
                    float2 sv = __half22float2(*(const __half2*)&acc[mi][ni][h]);
                    if (gcol != grow) {                  // only binds on diag tiles
                        s += __expf(sv.x);
                        a = fmaf(lv.x, sv.x, a);
                        b += lv.x;
                    }
                    if (gcol + 1 != grow) {
                        s += __expf(sv.y);
                        a = fmaf(lv.y, sv.y, a);
                        b += lv.y;
                    }
                }
                s += __shfl_xor_sync(0xffffffffu, s, 1);
                s += __shfl_xor_sync(0xffffffffu, s, 2);
                a += __shfl_xor_sync(0xffffffffu, a, 1);
                a += __shfl_xor_sync(0xffffffffu, a, 2);
                b += __shfl_xor_sync(0xffffffffu, b, 1);
                b += __shfl_xor_sync(0xffffffffu, b, 2);
                if ((lane & 3) == 0) {
                    g_ps[stripe * N_ROWS + grow] = s;
                    g_pa[stripe * N_ROWS + grow] = a;
                    g_pb[stripe * N_ROWS + grow] = b;
                }
            }
        }
    }

    // ---- pass 2 (off-diag only): column partials for n-block rows (dir-2) ----
    if (offdiag) {
        const int slot  = tm * 4 + warp_m * 2;
        const int zslot = slot + 1;                 // hole slot: zero-filled here
        #pragma unroll
        for (int ni = 0; ni < 4; ++ni) {
            const int gc0 = col0 + warp_n * 32 + ni * 8 + qcol;   // output rows gc0, gc0+1
            const float* lc0 = labels + (size_t)gc0 * N_ROWS;
            const float* lc1 = lc0 + N_ROWS;
            float s0 = 0.f, s1 = 0.f, a0 = 0.f, a1 = 0.f, b0 = 0.f, b1 = 0.f;
            #pragma unroll
            for (int mi = 0; mi < 4; ++mi) {
                #pragma unroll
                for (int h = 0; h < 2; ++h) {
                    const int grow = row0 + warp_m * 64 + mi * 16 + h * 8 + qrow;
                    float2 sv = __half22float2(*(const __half2*)&acc[mi][ni][h]);
                    float l0 = __ldcs(lc0 + grow);     // lbl[gc0][grow]
                    float l1 = __ldcs(lc1 + grow);     // lbl[gc0+1][grow]
                    s0 += __expf(sv.x);
                    s1 += __expf(sv.y);
                    a0 = fmaf(l0, sv.x, a0);
                    a1 = fmaf(l1, sv.y, a1);
                    b0 += l0;
                    b1 += l1;
                }
            }
            #pragma unroll
            for (int o = 4; o <= 16; o <<= 1) {
                s0 += __shfl_xor_sync(0xffffffffu, s0, o);
                s1 += __shfl_xor_sync(0xffffffffu, s1, o);
                a0 += __shfl_xor_sync(0xffffffffu, a0, o);
                a1 += __shfl_xor_sync(0xffffffffu, a1, o);
                b0 += __shfl_xor_sync(0xffffffffu, b0, o);
                b1 += __shfl_xor_sync(0xffffffffu, b1, o);
            }
            if (qrow == 0) {
                g_ps[slot * N_ROWS + gc0]     = s0;
                g_ps[slot * N_ROWS + gc0 + 1] = s1;
                g_pa[slot * N_ROWS + gc0]     = a0;
                g_pa[slot * N_ROWS + gc0 + 1] = a1;
                g_pb[slot * N_ROWS + gc0]     = b0;
                g_pb[slot * N_ROWS + gc0 + 1] = b1;
                // zero-fill the hole slot (replaces a standalone zero kernel)
                g_ps[zslot * N_ROWS + gc0]     = 0.f;
                g_ps[zslot * N_ROWS + gc0 + 1] = 0.f;
                g_pa[zslot * N_ROWS + gc0]     = 0.f;
                g_pa[zslot * N_ROWS + gc0 + 1] = 0.f;
                g_pb[zslot * N_ROWS + gc0]     = 0.f;
                g_pb[zslot * N_ROWS + gc0 + 1] = 0.f;
            }
        }
    }
}

// ------------------------------------------------------------------
// Kernel 3: per-row reduction of the 256 stripe partials + per-CTA loss
// partial + last-block final reduction. Deterministic fixed trees.
// ------------------------------------------------------------------
__global__ __launch_bounds__(256) void coref_rowloss_kernel(float* __restrict__ out) {
    const int rlane = threadIdx.x & 31;
    const int grp   = threadIdx.x >> 5;            // 0..7
    const int row   = blockIdx.x * 32 + rlane;
    float S = 0.f, A = 0.f, B = 0.f;
    #pragma unroll 8
    for (int k = 0; k < 32; ++k) {
        const int t = grp * 32 + k;
        S += g_ps[t * N_ROWS + row];
        A += g_pa[t * N_ROWS + row];
        B += g_pb[t * N_ROWS + row];
    }
    __shared__ float ss[8][32], sa[8][32], sb2[8][32];
    ss[grp][rlane] = S; sa[grp][rlane] = A; sb2[grp][rlane] = B;
    __syncthreads();
    if (grp == 0) {
        float St = 0.f, At = 0.f, Bt = 0.f;
        #pragma unroll
        for (int g = 0; g < 8; ++g) {
            St += ss[g][rlane]; At += sa[g][rlane]; Bt += sb2[g][rlane];
        }
        // loss_i = lse_i * B_i - A_i   (no max shift: |sim| <= ~5)
        float loss = logf(St) * Bt - At;
        #pragma unroll
        for (int o = 16; o > 0; o >>= 1) loss += __shfl_xor_sync(0xffffffffu, loss, o);

        unsigned last = 0;
        if (rlane == 0) {
            g_blocksum[blockIdx.x] = loss;
            __threadfence();                            // publish before counting
            unsigned old = atomicAdd(&g_done, 1u);
            last = (old == NRL_CTAS - 1) ? 1u : 0u;
        }
        last = __shfl_sync(0xffffffffu, last, 0);
        if (last) {
            __threadfence();                            // acquire all partials
            float v = 0.f;
            #pragma unroll
            for (int i = 0; i < NRL_CTAS / 32; ++i)     // fixed per-lane order
                v += g_blocksum[rlane + i * 32];
            #pragma unroll
            for (int o = 16; o > 0; o >>= 1) v += __shfl_xor_sync(0xffffffffu, v, o);
            if (rlane == 0) {
                out[0] = v * (1.0f / (float)N_ROWS);
                g_done = 0;                             // reset for next graph replay
            }
        }
    }
}

// ------------------------------------------------------------------
// Launcher (graph-capturable)
// ------------------------------------------------------------------
extern "C" void kernel_launch(void* const* d_in, const int* in_sizes, int n_in,
                              void* d_out, int out_size) {
    const float* embs   = (const float*)d_in[0];
    const float* labels = (const float*)d_in[1];
    if (n_in >= 2 && in_sizes[0] == N_ROWS * N_ROWS) {  // defensive input-order check
        const float* tmp = embs; embs = labels; labels = tmp;
    }
    float* out = (float*)d_out;

    cudaFuncSetAttribute(coref_main_kernel,
                         cudaFuncAttributeMaxDynamicSharedMemorySize, SMEM_BYTES);

    coref_norm_kernel<<<N_ROWS, 256>>>(embs);
    coref_main_kernel<<<NTRI, THREADS, SMEM_BYTES>>>(labels);
    coref_rowloss_kernel<<<NRL_CTAS, 256>>>(out);
}

// round 14
// speedup vs baseline: 2.2031x; 1.0256x over previous
#include <cuda_runtime.h>
#include <cuda_fp16.h>
#include <cstdint>

// ------------------------------------------------------------------
// Problem constants
// ------------------------------------------------------------------
constexpr int N_ROWS = 8192;
constexpr int DIM    = 1024;
constexpr float SQRT_INV_TEMP = 2.23606797749978969f;   // sqrt(1/0.2)

constexpr int TM = 128;               // CTA tile rows
constexpr int TN = 128;               // CTA tile cols
constexpr int TK = 64;                // fp16 K elems per stage (128 B rows)
constexpr int STAGES  = 3;
constexpr int THREADS = 256;          // 8 warps, 2 (M) x 4 (N)
constexpr int NKC = DIM / TK;         // 16 K chunks

constexpr int A_BYTES   = TM * TK * 2;            // 16 KB
constexpr int B_BYTES   = TN * TK * 2;            // 16 KB
constexpr int STG_BYTES = A_BYTES + B_BYTES;      // 32 KB
constexpr int SMEM_BYTES = STAGES * STG_BYTES;    // 96 KB

constexpr int NTILE   = N_ROWS / TM;              // 64
constexpr int NTRI    = NTILE * (NTILE + 1) / 2;  // 2080 upper-tri tiles
constexpr int NSLOT   = NTILE;                    // 64 scratch slots per row
constexpr int NRL_CTAS = N_ROWS / 32;             // 256 rowloss CTAs
// Per row r in row-tile tr: dir-1 (tiles (tr,tn), tn>=tr) writes slots tn>=tr;
// dir-2 (tiles (tm,tr), tm<tr) writes slots tm<tr. Union = all 64 slots,
// each exactly once -> no zero-fill needed.

// ------------------------------------------------------------------
// Device scratch (static globals: allocation-free)
// ------------------------------------------------------------------
__device__ __half g_x[(size_t)N_ROWS * DIM];          // normalized * sqrt(5), fp16
__device__ float g_ps[NSLOT * N_ROWS];                // partial sum exp(sim)
__device__ float g_pa[NSLOT * N_ROWS];                // partial sum lbl*sim
__device__ float g_pb[NSLOT * N_ROWS];                // partial sum lbl
__device__ float g_blocksum[NRL_CTAS];                // per-rowloss-CTA loss partials
__device__ unsigned g_done;                           // rowloss completion counter

// ------------------------------------------------------------------
// PTX helpers
// ------------------------------------------------------------------
__device__ __forceinline__ uint32_t smem_u32(const void* p) {
    uint32_t a;
    asm("{ .reg .u64 t; cvta.to.shared.u64 t, %1; cvt.u32.u64 %0, t; }" : "=r"(a) : "l"(p));
    return a;
}

__device__ __forceinline__ void cp_async16(uint32_t dst, const void* src) {
    asm volatile("{ .reg .u64 g; cvta.to.global.u64 g, %1; "
                 "cp.async.cg.shared.global [%0], [g], 16; }"
                 :: "r"(dst), "l"(src) : "memory");
}
#define CP_COMMIT() asm volatile("cp.async.commit_group;" ::: "memory")
#define CP_WAIT(N)  asm volatile("cp.async.wait_group %0;" :: "n"(N) : "memory")

#define LDSM_X4(R0, R1, R2, R3, ADDR) \
    asm volatile("ldmatrix.sync.aligned.m8n8.x4.shared.b16 {%0,%1,%2,%3}, [%4];" \
                 : "=r"(R0), "=r"(R1), "=r"(R2), "=r"(R3) : "r"(ADDR))

// fp16-accumulator HMMA: D reg h = (c0,c1) for row-group h (rows qrow/qrow+8)
__device__ __forceinline__ void mma_f16(uint32_t* d, const uint32_t* a, const uint32_t* b) {
    asm volatile(
        "mma.sync.aligned.m16n8k16.row.col.f16.f16.f16.f16 "
        "{%0,%1}, {%2,%3,%4,%5}, {%6,%7}, {%0,%1};"
        : "+r"(d[0]), "+r"(d[1])
        : "r"(a[0]), "r"(a[1]), "r"(a[2]), "r"(a[3]), "r"(b[0]), "r"(b[1]));
}

// ------------------------------------------------------------------
// Kernel 1: row-normalize, fold sqrt(1/T), cast to fp16 (float4 loads)
// ------------------------------------------------------------------
__global__ __launch_bounds__(256) void coref_norm_kernel(const float* __restrict__ e) {
    const int row = blockIdx.x, t = threadIdx.x;
    const float4 v = ((const float4*)(e + (size_t)row * DIM))[t];
    float ss = v.x * v.x + v.y * v.y + v.z * v.z + v.w * v.w;
    #pragma unroll
    for (int o = 16; o > 0; o >>= 1) ss += __shfl_xor_sync(0xffffffffu, ss, o);
    __shared__ float ws[8];
    if ((t & 31) == 0) ws[t >> 5] = ss;
    __syncthreads();
    float tot = ws[0] + ws[1] + ws[2] + ws[3] + ws[4] + ws[5] + ws[6] + ws[7];
    float scale = SQRT_INV_TEMP / fmaxf(sqrtf(tot), 1e-8f);
    __half2 h01 = __floats2half2_rn(v.x * scale, v.y * scale);
    __half2 h23 = __floats2half2_rn(v.z * scale, v.w * scale);
    uint2 w;
    w.x = *(const unsigned*)&h01;
    w.y = *(const unsigned*)&h23;
    ((uint2*)(g_x + (size_t)row * DIM))[t] = w;
}

// ------------------------------------------------------------------
// Kernel 2: fused upper-triangular tile GEMM (mma.sync f16 accum)
//           + two-direction CTA-reduced softmax/label epilogue
// ------------------------------------------------------------------
__device__ __forceinline__ void load_stage(uint32_t sbuf, int row_a, int row_b,
                                           int kc, int tid) {
    const __half* gA = g_x + (size_t)row_a * DIM + kc * TK;
    #pragma unroll
    for (int i = 0; i < 4; ++i) {                 // A: 128 rows x 8 chunks (16B)
        int id = tid + (i << 8);
        int r = id >> 3, c = id & 7;
        uint32_t sw = (uint32_t)(r * 128) + (uint32_t)((c ^ (r & 7)) << 4);
        cp_async16(sbuf + sw, gA + (size_t)r * DIM + c * 8);
    }
    const __half* gB = g_x + (size_t)row_b * DIM + kc * TK;
    uint32_t bb = sbuf + A_BYTES;
    #pragma unroll
    for (int i = 0; i < 4; ++i) {                 // B: 128 rows x 8 chunks
        int id = tid + (i << 8);
        int r = id >> 3, c = id & 7;
        uint32_t sw = (uint32_t)(r * 128) + (uint32_t)((c ^ (r & 7)) << 4);
        cp_async16(bb + sw, gB + (size_t)r * DIM + c * 8);
    }
}

__global__ __launch_bounds__(THREADS, 2)
void coref_main_kernel(const float* __restrict__ labels) {
    extern __shared__ char smem_raw[];
    const uint32_t sb = smem_u32(smem_raw);

    const int tid  = threadIdx.x;
    const int lane = tid & 31;
    const int warp = tid >> 5;
    const int warp_m = warp & 1;        // 0..1 -> 64-row half
    const int warp_n = warp >> 1;       // 0..3 -> 32-col stripe

    // Decode blockIdx.x -> upper-triangular (tm, tn), tm <= tn
    int brem = blockIdx.x, tm = 0;
    while (brem >= NTILE - tm) { brem -= NTILE - tm; ++tm; }
    const int tn = tm + brem;
    const int row0 = tm * TM;
    const int col0 = tn * TN;
    const bool offdiag = (tm != tn);

    // Prologue: prefetch stages 0,1
    load_stage(sb,              row0, col0, 0, tid); CP_COMMIT();
    load_stage(sb + STG_BYTES,  row0, col0, 1, tid); CP_COMMIT();

    uint32_t acc[4][4][2];                       // [mi][ni][rowgroup] f16x2 accum
    #pragma unroll
    for (int mi = 0; mi < 4; ++mi)
        #pragma unroll
        for (int ni = 0; ni < 4; ++ni) {
            acc[mi][ni][0] = 0u;
            acc[mi][ni][1] = 0u;
        }

    // ldmatrix lane addressing
    const int a_row_in = (lane & 7) + ((lane >> 3) & 1) * 8;
    const int a_hi     = lane >> 4;
    const int b_row_in = (lane & 7) + (lane >> 4) * 8;
    const int b_hi     = (lane >> 3) & 1;

    int a_rowbyte[4], a_rx[4];
    #pragma unroll
    for (int mi = 0; mi < 4; ++mi) {
        int r = warp_m * 64 + mi * 16 + a_row_in;
        a_rowbyte[mi] = r * 128;
        a_rx[mi] = r & 7;
    }
    int b_rowbyte[2], b_rx[2];
    #pragma unroll
    for (int g = 0; g < 2; ++g) {
        int r = warp_n * 32 + g * 16 + b_row_in;
        b_rowbyte[g] = r * 128;
        b_rx[g] = r & 7;
    }

    for (int kc = 0; kc < NKC; ++kc) {
        if (kc == NKC - 1) { CP_WAIT(0); } else { CP_WAIT(1); }
        __syncthreads();

        if (kc + 2 < NKC) {
            load_stage(sb + ((kc + 2) % STAGES) * STG_BYTES, row0, col0, kc + 2, tid);
            CP_COMMIT();
        }

        const uint32_t sA = sb + (kc % STAGES) * STG_BYTES;
        const uint32_t sB = sA + A_BYTES;

        #pragma unroll
        for (int kk = 0; kk < 4; ++kk) {
            const int kk2 = kk * 2;
            uint32_t Af[4][4], Bf[4][2];
            #pragma unroll
            for (int mi = 0; mi < 4; ++mi) {
                uint32_t addr = sA + a_rowbyte[mi]
                              + (uint32_t)(((kk2 + a_hi) ^ a_rx[mi]) << 4);
                LDSM_X4(Af[mi][0], Af[mi][1], Af[mi][2], Af[mi][3], addr);
            }
            #pragma unroll
            for (int g = 0; g < 2; ++g) {
                uint32_t q0, q1, q2, q3;
                uint32_t addr = sB + b_rowbyte[g]
                              + (uint32_t)(((kk2 + b_hi) ^ b_rx[g]) << 4);
                LDSM_X4(q0, q1, q2, q3, addr);
                Bf[g * 2 + 0][0] = q0; Bf[g * 2 + 0][1] = q1;
                Bf[g * 2 + 1][0] = q2; Bf[g * 2 + 1][1] = q3;
            }
            #pragma unroll
            for (int mi = 0; mi < 4; ++mi)
                #pragma unroll
                for (int ni = 0; ni < 4; ++ni)
                    mma_f16(acc[mi][ni], Af[mi], Bf[ni]);
        }
    }

    // ---------------- epilogue ----------------
    // f16 fragment: reg h = (cols qcol, qcol+1) of row (qrow + 8h)
    const int qrow = lane >> 2;        // 0..7
    const int qcol = (lane & 3) * 2;   // 0,2,4,6

    // smem reduction buffers overlay the (now idle) pipeline stages.
    // red[0..511]=s[warp_seg][128], red[512..1023]=a, red[1024..1535]=b
    float* red = (float*)smem_raw;
    __syncthreads();   // stage-0 LDSM reads (kc=15) must drain before overwrite

    // ---- pass 1: row partials for m-block rows (dir-1), CTA-reduced -> slot tn ----
    #pragma unroll
    for (int mi = 0; mi < 4; ++mi) {
        #pragma unroll
        for (int h = 0; h < 2; ++h) {
            const int rloc = warp_m * 64 + mi * 16 + qrow + h * 8;
            const int grow = row0 + rloc;
            const float* lrow = labels + (size_t)grow * N_ROWS + col0 + warp_n * 32;
            float s = 0.f, a = 0.f, b = 0.f;
            #pragma unroll
            for (int ni = 0; ni < 4; ++ni) {
                const int gcol = col0 + warp_n * 32 + ni * 8 + qcol;
                float2 lv = __ldcs((const float2*)(lrow + ni * 8 + qcol));
                float2 sv = __half22float2(*(const __half2*)&acc[mi][ni][h]);
                if (gcol != grow) {                  // only binds on diag tiles
                    s += __expf(sv.x);
                    a = fmaf(lv.x, sv.x, a);
                    b += lv.x;
                }
                if (gcol + 1 != grow) {
                    s += __expf(sv.y);
                    a = fmaf(lv.y, sv.y, a);
                    b += lv.y;
                }
            }
            s += __shfl_xor_sync(0xffffffffu, s, 1);
            s += __shfl_xor_sync(0xffffffffu, s, 2);
            a += __shfl_xor_sync(0xffffffffu, a, 1);
            a += __shfl_xor_sync(0xffffffffu, a, 2);
            b += __shfl_xor_sync(0xffffffffu, b, 1);
            b += __shfl_xor_sync(0xffffffffu, b, 2);
            if ((lane & 3) == 0) {
                red[       warp_n * 128 + rloc] = s;
                red[512  + warp_n * 128 + rloc] = a;
                red[1024 + warp_n * 128 + rloc] = b;
            }
        }
    }
    __syncthreads();
    if (tid < 128) {
        float S = red[tid]        + red[128 + tid]
                + red[256 + tid]  + red[384 + tid];
        float A = red[512 + tid]  + red[512 + 128 + tid]
                + red[512 + 256 + tid] + red[512 + 384 + tid];
        float B = red[1024 + tid] + red[1024 + 128 + tid]
                + red[1024 + 256 + tid] + red[1024 + 384 + tid];
        g_ps[tn * N_ROWS + row0 + tid] = S;
        g_pa[tn * N_ROWS + row0 + tid] = A;
        g_pb[tn * N_ROWS + row0 + tid] = B;
    }

    // ---- pass 2 (off-diag only): column partials (dir-2), CTA-reduced -> slot tm ----
    if (offdiag) {
        __syncthreads();   // pass-1 smem reads done before overwrite
        #pragma unroll
        for (int ni = 0; ni < 4; ++ni) {
            const int gc0 = col0 + warp_n * 32 + ni * 8 + qcol;   // output rows gc0, gc0+1
            const float* lc0 = labels + (size_t)gc0 * N_ROWS;
            const float* lc1 = lc0 + N_ROWS;
            float s0 = 0.f, s1 = 0.f, a0 = 0.f, a1 = 0.f, b0 = 0.f, b1 = 0.f;
            #pragma unroll
            for (int mi = 0; mi < 4; ++mi) {
                #pragma unroll
                for (int h = 0; h < 2; ++h) {
                    const int grow = row0 + warp_m * 64 + mi * 16 + h * 8 + qrow;
                    float2 sv = __half22float2(*(const __half2*)&acc[mi][ni][h]);
                    float l0 = __ldcs(lc0 + grow);     // lbl[gc0][grow]
                    float l1 = __ldcs(lc1 + grow);     // lbl[gc0+1][grow]
                    s0 += __expf(sv.x);
                    s1 += __expf(sv.y);
                    a0 = fmaf(l0, sv.x, a0);
                    a1 = fmaf(l1, sv.y, a1);
                    b0 += l0;
                    b1 += l1;
                }
            }
            #pragma unroll
            for (int o = 4; o <= 16; o <<= 1) {
                s0 += __shfl_xor_sync(0xffffffffu, s0, o);
                s1 += __shfl_xor_sync(0xffffffffu, s1, o);
                a0 += __shfl_xor_sync(0xffffffffu, a0, o);
                a1 += __shfl_xor_sync(0xffffffffu, a1, o);
                b0 += __shfl_xor_sync(0xffffffffu, b0, o);
                b1 += __shfl_xor_sync(0xffffffffu, b1, o);
            }
            if (qrow == 0) {                        // lanes 0..3 hold results
                const int cloc = warp_n * 32 + ni * 8 + qcol;   // 0..127
                red[       warp_m * 128 + cloc]     = s0;
                red[       warp_m * 128 + cloc + 1] = s1;
                red[512  + warp_m * 128 + cloc]     = a0;
                red[512  + warp_m * 128 + cloc + 1] = a1;
                red[1024 + warp_m * 128 + cloc]     = b0;
                red[1024 + warp_m * 128 + cloc + 1] = b1;
            }
        }
        __syncthreads();
        if (tid < 128) {
            float S = red[tid]        + red[128 + tid];
            float A = red[512 + tid]  + red[512 + 128 + tid];
            float B = red[1024 + tid] + red[1024 + 128 + tid];
            g_ps[tm * N_ROWS + col0 + tid] = S;
            g_pa[tm * N_ROWS + col0 + tid] = A;
            g_pb[tm * N_ROWS + col0 + tid] = B;
        }
    }
}

// ------------------------------------------------------------------
// Kernel 3: per-row reduction of the 64 slot partials + per-CTA loss
// partial + last-block final reduction. Deterministic fixed trees.
// 256 CTAs x 256 threads; tid%32 -> row (coalesced), tid/32 -> 8 slots.
// ------------------------------------------------------------------
__global__ __launch_bounds__(256) void coref_rowloss_kernel(float* __restrict__ out) {
    const int rlane = threadIdx.x & 31;
    const int grp   = threadIdx.x >> 5;            // 0..7
    const int row   = blockIdx.x * 32 + rlane;
    float S = 0.f, A = 0.f, B = 0.f;
    #pragma unroll
    for (int k = 0; k < 8; ++k) {
        const int t = grp * 8 + k;
        S += g_ps[t * N_ROWS + row];
        A += g_pa[t * N_ROWS + row];
        B += g_pb[t * N_ROWS + row];
    }
    __shared__ float ss[8][32], sa[8][32], sb2[8][32];
    ss[grp][rlane] = S; sa[grp][rlane] = A; sb2[grp][rlane] = B;
    __syncthreads();
    if (grp == 0) {
        float St = 0.f, At = 0.f, Bt = 0.f;
        #pragma unroll
        for (int g = 0; g < 8; ++g) {
            St += ss[g][rlane]; At += sa[g][rlane]; Bt += sb2[g][rlane];
        }
        // loss_i = lse_i * B_i - A_i   (no max shift: |sim| <= ~5)
        float loss = logf(St) * Bt - At;
        #pragma unroll
        for (int o = 16; o > 0; o >>= 1) loss += __shfl_xor_sync(0xffffffffu, loss, o);

        unsigned last = 0;
        if (rlane == 0) {
            g_blocksum[blockIdx.x] = loss;
            __threadfence();                            // publish before counting
            unsigned old = atomicAdd(&g_done, 1u);
            last = (old == NRL_CTAS - 1) ? 1u : 0u;
        }
        last = __shfl_sync(0xffffffffu, last, 0);
        if (last) {
            __threadfence();                            // acquire all partials
            float v = 0.f;
            #pragma unroll
            for (int i = 0; i < NRL_CTAS / 32; ++i)     // fixed per-lane order
                v += g_blocksum[rlane + i * 32];
            #pragma unroll
            for (int o = 16; o > 0; o >>= 1) v += __shfl_xor_sync(0xffffffffu, v, o);
            if (rlane == 0) {
                out[0] = v * (1.0f / (float)N_ROWS);
                g_done = 0;                             // reset for next graph replay
            }
        }
    }
}

// ------------------------------------------------------------------
// Launcher (graph-capturable)
// ------------------------------------------------------------------
extern "C" void kernel_launch(void* const* d_in, const int* in_sizes, int n_in,
                              void* d_out, int out_size) {
    const float* embs   = (const float*)d_in[0];
    const float* labels = (const float*)d_in[1];
    if (n_in >= 2 && in_sizes[0] == N_ROWS * N_ROWS) {  // defensive input-order check
        const float* tmp = embs; embs = labels; labels = tmp;
    }
    float* out = (float*)d_out;

    cudaFuncSetAttribute(coref_main_kernel,
                         cudaFuncAttributeMaxDynamicSharedMemorySize, SMEM_BYTES);

    coref_norm_kernel<<<N_ROWS, 256>>>(embs);
    coref_main_kernel<<<NTRI, THREADS, SMEM_BYTES>>>(labels);
    coref_rowloss_kernel<<<NRL_CTAS, 256>>>(out);
}

// round 15
// speedup vs baseline: 2.2432x; 1.0182x over previous
#include <cuda_runtime.h>
#include <cuda_fp16.h>
#include <cstdint>

// ------------------------------------------------------------------
// Problem constants
// ------------------------------------------------------------------
constexpr int N_ROWS = 8192;
constexpr int DIM    = 1024;
constexpr float SQRT_INV_TEMP = 2.23606797749978969f;   // sqrt(1/0.2)

constexpr int TM = 128;               // CTA tile rows
constexpr int TN = 128;               // CTA tile cols
constexpr int TK = 64;                // fp16 K elems per stage (128 B rows)
constexpr int STAGES  = 3;
constexpr int THREADS = 256;          // 8 warps, 2 (M) x 4 (N)
constexpr int NKC = DIM / TK;         // 16 K chunks

constexpr int A_BYTES   = TM * TK * 2;            // 16 KB
constexpr int B_BYTES   = TN * TK * 2;            // 16 KB
constexpr int STG_BYTES = A_BYTES + B_BYTES;      // 32 KB
constexpr int SMEM_BYTES = STAGES * STG_BYTES;    // 96 KB

constexpr int NTILE   = N_ROWS / TM;              // 64
constexpr int NTRI    = NTILE * (NTILE + 1) / 2;  // 2080 upper-tri tiles
constexpr int NSLOT   = NTILE;                    // 64 scratch slots per row
constexpr int NRL_CTAS = N_ROWS / 32;             // 256 rowloss CTAs
// Per row r in row-tile tr: dir-1 (tiles (tr,tn), tn>=tr) writes slots tn>=tr;
// dir-2 (tiles (tm,tr), tm<tr) writes slots tm<tr. Union = all 64 slots,
// each exactly once -> no zero-fill needed.

// ------------------------------------------------------------------
// Device scratch (static globals: allocation-free)
// ------------------------------------------------------------------
__device__ __half g_x[(size_t)N_ROWS * DIM];          // normalized * sqrt(5), fp16
__device__ float g_ps[NSLOT * N_ROWS];                // partial sum exp(sim)
__device__ float g_pa[NSLOT * N_ROWS];                // partial sum lbl*sim
__device__ float g_pb[NSLOT * N_ROWS];                // partial sum lbl
__device__ float g_blocksum[NRL_CTAS];                // per-rowloss-CTA loss partials
__device__ unsigned g_done;                           // rowloss completion counter

// ------------------------------------------------------------------
// PTX helpers
// ------------------------------------------------------------------
__device__ __forceinline__ uint32_t smem_u32(const void* p) {
    uint32_t a;
    asm("{ .reg .u64 t; cvta.to.shared.u64 t, %1; cvt.u32.u64 %0, t; }" : "=r"(a) : "l"(p));
    return a;
}

__device__ __forceinline__ void cp_async16(uint32_t dst, const void* src) {
    asm volatile("{ .reg .u64 g; cvta.to.global.u64 g, %1; "
                 "cp.async.cg.shared.global [%0], [g], 16; }"
                 :: "r"(dst), "l"(src) : "memory");
}
#define CP_COMMIT() asm volatile("cp.async.commit_group;" ::: "memory")
#define CP_WAIT(N)  asm volatile("cp.async.wait_group %0;" :: "n"(N) : "memory")

#define LDSM_X4(R0, R1, R2, R3, ADDR) \
    asm volatile("ldmatrix.sync.aligned.m8n8.x4.shared.b16 {%0,%1,%2,%3}, [%4];" \
                 : "=r"(R0), "=r"(R1), "=r"(R2), "=r"(R3) : "r"(ADDR))

// fp16-accumulator HMMA: D reg h = (c0,c1) for row-group h (rows qrow/qrow+8)
__device__ __forceinline__ void mma_f16(uint32_t* d, const uint32_t* a, const uint32_t* b) {
    asm volatile(
        "mma.sync.aligned.m16n8k16.row.col.f16.f16.f16.f16 "
        "{%0,%1}, {%2,%3,%4,%5}, {%6,%7}, {%0,%1};"
        : "+r"(d[0]), "+r"(d[1])
        : "r"(a[0]), "r"(a[1]), "r"(a[2]), "r"(a[3]), "r"(b[0]), "r"(b[1]));
}

// ------------------------------------------------------------------
// Kernel 1: row-normalize, fold sqrt(1/T), cast to fp16.
// Warp-per-row: 8 warps/CTA, no block reduce, MLP-8 float4 loads.
// ------------------------------------------------------------------
__global__ __launch_bounds__(256) void coref_norm_kernel(const float* __restrict__ e) {
    const int lane = threadIdx.x & 31;
    const int row  = blockIdx.x * 8 + (threadIdx.x >> 5);
    const float4* r4 = (const float4*)(e + (size_t)row * DIM);   // 256 float4/row

    float4 v[8];
    float ss = 0.f;
    #pragma unroll
    for (int i = 0; i < 8; ++i) {
        v[i] = r4[i * 32 + lane];
        ss += v[i].x * v[i].x + v[i].y * v[i].y + v[i].z * v[i].z + v[i].w * v[i].w;
    }
    #pragma unroll
    for (int o = 16; o > 0; o >>= 1) ss += __shfl_xor_sync(0xffffffffu, ss, o);
    const float scale = SQRT_INV_TEMP / fmaxf(sqrtf(ss), 1e-8f);

    uint2* o4 = (uint2*)(g_x + (size_t)row * DIM);               // 8B per float4-worth
    #pragma unroll
    for (int i = 0; i < 8; ++i) {
        __half2 h01 = __floats2half2_rn(v[i].x * scale, v[i].y * scale);
        __half2 h23 = __floats2half2_rn(v[i].z * scale, v[i].w * scale);
        uint2 w;
        w.x = *(const unsigned*)&h01;
        w.y = *(const unsigned*)&h23;
        o4[i * 32 + lane] = w;
    }
}

// ------------------------------------------------------------------
// Kernel 2: fused upper-triangular tile GEMM (mma.sync f16 accum)
//           + two-direction CTA-reduced softmax/label epilogue
// (byte-identical to the 227.8us R14 version — register-critical)
// ------------------------------------------------------------------
__device__ __forceinline__ void load_stage(uint32_t sbuf, int row_a, int row_b,
                                           int kc, int tid) {
    const __half* gA = g_x + (size_t)row_a * DIM + kc * TK;
    #pragma unroll
    for (int i = 0; i < 4; ++i) {                 // A: 128 rows x 8 chunks (16B)
        int id = tid + (i << 8);
        int r = id >> 3, c = id & 7;
        uint32_t sw = (uint32_t)(r * 128) + (uint32_t)((c ^ (r & 7)) << 4);
        cp_async16(sbuf + sw, gA + (size_t)r * DIM + c * 8);
    }
    const __half* gB = g_x + (size_t)row_b * DIM + kc * TK;
    uint32_t bb = sbuf + A_BYTES;
    #pragma unroll
    for (int i = 0; i < 4; ++i) {                 // B: 128 rows x 8 chunks
        int id = tid + (i << 8);
        int r = id >> 3, c = id & 7;
        uint32_t sw = (uint32_t)(r * 128) + (uint32_t)((c ^ (r & 7)) << 4);
        cp_async16(bb + sw, gB + (size_t)r * DIM + c * 8);
    }
}

__global__ __launch_bounds__(THREADS, 2)
void coref_main_kernel(const float* __restrict__ labels) {
    extern __shared__ char smem_raw[];
    const uint32_t sb = smem_u32(smem_raw);

    const int tid  = threadIdx.x;
    const int lane = tid & 31;
    const int warp = tid >> 5;
    const int warp_m = warp & 1;        // 0..1 -> 64-row half
    const int warp_n = warp >> 1;       // 0..3 -> 32-col stripe

    // Decode blockIdx.x -> upper-triangular (tm, tn), tm <= tn
    int brem = blockIdx.x, tm = 0;
    while (brem >= NTILE - tm) { brem -= NTILE - tm; ++tm; }
    const int tn = tm + brem;
    const int row0 = tm * TM;
    const int col0 = tn * TN;
    const bool offdiag = (tm != tn);

    // Prologue: prefetch stages 0,1
    load_stage(sb,              row0, col0, 0, tid); CP_COMMIT();
    load_stage(sb + STG_BYTES,  row0, col0, 1, tid); CP_COMMIT();

    uint32_t acc[4][4][2];                       // [mi][ni][rowgroup] f16x2 accum
    #pragma unroll
    for (int mi = 0; mi < 4; ++mi)
        #pragma unroll
        for (int ni = 0; ni < 4; ++ni) {
            acc[mi][ni][0] = 0u;
            acc[mi][ni][1] = 0u;
        }

    // ldmatrix lane addressing
    const int a_row_in = (lane & 7) + ((lane >> 3) & 1) * 8;
    const int a_hi     = lane >> 4;
    const int b_row_in = (lane & 7) + (lane >> 4) * 8;
    const int b_hi     = (lane >> 3) & 1;

    int a_rowbyte[4], a_rx[4];
    #pragma unroll
    for (int mi = 0; mi < 4; ++mi) {
        int r = warp_m * 64 + mi * 16 + a_row_in;
        a_rowbyte[mi] = r * 128;
        a_rx[mi] = r & 7;
    }
    int b_rowbyte[2], b_rx[2];
    #pragma unroll
    for (int g = 0; g < 2; ++g) {
        int r = warp_n * 32 + g * 16 + b_row_in;
        b_rowbyte[g] = r * 128;
        b_rx[g] = r & 7;
    }

    for (int kc = 0; kc < NKC; ++kc) {
        if (kc == NKC - 1) { CP_WAIT(0); } else { CP_WAIT(1); }
        __syncthreads();

        if (kc + 2 < NKC) {
            load_stage(sb + ((kc + 2) % STAGES) * STG_BYTES, row0, col0, kc + 2, tid);
            CP_COMMIT();
        }

        const uint32_t sA = sb + (kc % STAGES) * STG_BYTES;
        const uint32_t sB = sA + A_BYTES;

        #pragma unroll
        for (int kk = 0; kk < 4; ++kk) {
            const int kk2 = kk * 2;
            uint32_t Af[4][4], Bf[4][2];
            #pragma unroll
            for (int mi = 0; mi < 4; ++mi) {
                uint32_t addr = sA + a_rowbyte[mi]
                              + (uint32_t)(((kk2 + a_hi) ^ a_rx[mi]) << 4);
                LDSM_X4(Af[mi][0], Af[mi][1], Af[mi][2], Af[mi][3], addr);
            }
            #pragma unroll
            for (int g = 0; g < 2; ++g) {
                uint32_t q0, q1, q2, q3;
                uint32_t addr = sB + b_rowbyte[g]
                              + (uint32_t)(((kk2 + b_hi) ^ b_rx[g]) << 4);
                LDSM_X4(q0, q1, q2, q3, addr);
                Bf[g * 2 + 0][0] = q0; Bf[g * 2 + 0][1] = q1;
                Bf[g * 2 + 1][0] = q2; Bf[g * 2 + 1][1] = q3;
            }
            #pragma unroll
            for (int mi = 0; mi < 4; ++mi)
                #pragma unroll
                for (int ni = 0; ni < 4; ++ni)
                    mma_f16(acc[mi][ni], Af[mi], Bf[ni]);
        }
    }

    // ---------------- epilogue ----------------
    // f16 fragment: reg h = (cols qcol, qcol+1) of row (qrow + 8h)
    const int qrow = lane >> 2;        // 0..7
    const int qcol = (lane & 3) * 2;   // 0,2,4,6

    // smem reduction buffers overlay the (now idle) pipeline stages.
    // red[0..511]=s[warp_seg][128], red[512..1023]=a, red[1024..1535]=b
    float* red = (float*)smem_raw;
    __syncthreads();   // stage-0 LDSM reads (kc=15) must drain before overwrite

    // ---- pass 1: row partials for m-block rows (dir-1), CTA-reduced -> slot tn ----
    #pragma unroll
    for (int mi = 0; mi < 4; ++mi) {
        #pragma unroll
        for (int h = 0; h < 2; ++h) {
            const int rloc = warp_m * 64 + mi * 16 + qrow + h * 8;
            const int grow = row0 + rloc;
            const float* lrow = labels + (size_t)grow * N_ROWS + col0 + warp_n * 32;
            float s = 0.f, a = 0.f, b = 0.f;
            #pragma unroll
            for (int ni = 0; ni < 4; ++ni) {
                const int gcol = col0 + warp_n * 32 + ni * 8 + qcol;
                float2 lv = __ldcs((const float2*)(lrow + ni * 8 + qcol));
                float2 sv = __half22float2(*(const __half2*)&acc[mi][ni][h]);
                if (gcol != grow) {                  // only binds on diag tiles
                    s += __expf(sv.x);
                    a = fmaf(lv.x, sv.x, a);
                    b += lv.x;
                }
                if (gcol + 1 != grow) {
                    s += __expf(sv.y);
                    a = fmaf(lv.y, sv.y, a);
                    b += lv.y;
                }
            }
            s += __shfl_xor_sync(0xffffffffu, s, 1);
            s += __shfl_xor_sync(0xffffffffu, s, 2);
            a += __shfl_xor_sync(0xffffffffu, a, 1);
            a += __shfl_xor_sync(0xffffffffu, a, 2);
            b += __shfl_xor_sync(0xffffffffu, b, 1);
            b += __shfl_xor_sync(0xffffffffu, b, 2);
            if ((lane & 3) == 0) {
                red[       warp_n * 128 + rloc] = s;
                red[512  + warp_n * 128 + rloc] = a;
                red[1024 + warp_n * 128 + rloc] = b;
            }
        }
    }
    __syncthreads();
    if (tid < 128) {
        float S = red[tid]        + red[128 + tid]
                + red[256 + tid]  + red[384 + tid];
        float A = red[512 + tid]  + red[512 + 128 + tid]
                + red[512 + 256 + tid] + red[512 + 384 + tid];
        float B = red[1024 + tid] + red[1024 + 128 + tid]
                + red[1024 + 256 + tid] + red[1024 + 384 + tid];
        g_ps[tn * N_ROWS + row0 + tid] = S;
        g_pa[tn * N_ROWS + row0 + tid] = A;
        g_pb[tn * N_ROWS + row0 + tid] = B;
    }

    // ---- pass 2 (off-diag only): column partials (dir-2), CTA-reduced -> slot tm ----
    if (offdiag) {
        __syncthreads();   // pass-1 smem reads done before overwrite
        #pragma unroll
        for (int ni = 0; ni < 4; ++ni) {
            const int gc0 = col0 + warp_n * 32 + ni * 8 + qcol;   // output rows gc0, gc0+1
            const float* lc0 = labels + (size_t)gc0 * N_ROWS;
            const float* lc1 = lc0 + N_ROWS;
            float s0 = 0.f, s1 = 0.f, a0 = 0.f, a1 = 0.f, b0 = 0.f, b1 = 0.f;
            #pragma unroll
            for (int mi = 0; mi < 4; ++mi) {
                #pragma unroll
                for (int h = 0; h < 2; ++h) {
                    const int grow = row0 + warp_m * 64 + mi * 16 + h * 8 + qrow;
                    float2 sv = __half22float2(*(const __half2*)&acc[mi][ni][h]);
                    float l0 = __ldcs(lc0 + grow);     // lbl[gc0][grow]
                    float l1 = __ldcs(lc1 + grow);     // lbl[gc0+1][grow]
                    s0 += __expf(sv.x);
                    s1 += __expf(sv.y);
                    a0 = fmaf(l0, sv.x, a0);
                    a1 = fmaf(l1, sv.y, a1);
                    b0 += l0;
                    b1 += l1;
                }
            }
            #pragma unroll
            for (int o = 4; o <= 16; o <<= 1) {
                s0 += __shfl_xor_sync(0xffffffffu, s0, o);
                s1 += __shfl_xor_sync(0xffffffffu, s1, o);
                a0 += __shfl_xor_sync(0xffffffffu, a0, o);
                a1 += __shfl_xor_sync(0xffffffffu, a1, o);
                b0 += __shfl_xor_sync(0xffffffffu, b0, o);
                b1 += __shfl_xor_sync(0xffffffffu, b1, o);
            }
            if (qrow == 0) {                        // lanes 0..3 hold results
                const int cloc = warp_n * 32 + ni * 8 + qcol;   // 0..127
                red[       warp_m * 128 + cloc]     = s0;
                red[       warp_m * 128 + cloc + 1] = s1;
                red[512  + warp_m * 128 + cloc]     = a0;
                red[512  + warp_m * 128 + cloc + 1] = a1;
                red[1024 + warp_m * 128 + cloc]     = b0;
                red[1024 + warp_m * 128 + cloc + 1] = b1;
            }
        }
        __syncthreads();
        if (tid < 128) {
            float S = red[tid]        + red[128 + tid];
            float A = red[512 + tid]  + red[512 + 128 + tid];
            float B = red[1024 + tid] + red[1024 + 128 + tid];
            g_ps[tm * N_ROWS + col0 + tid] = S;
            g_pa[tm * N_ROWS + col0 + tid] = A;
            g_pb[tm * N_ROWS + col0 + tid] = B;
        }
    }
}

// ------------------------------------------------------------------
// Kernel 3: per-row reduction of the 64 slot partials + per-CTA loss
// partial + last-block final reduction. Deterministic fixed trees.
// 256 CTAs x 256 threads; tid%32 -> row (coalesced), tid/32 -> 8 slots.
// ------------------------------------------------------------------
__global__ __launch_bounds__(256) void coref_rowloss_kernel(float* __restrict__ out) {
    const int rlane = threadIdx.x & 31;
    const int grp   = threadIdx.x >> 5;            // 0..7
    const int row   = blockIdx.x * 32 + rlane;
    float S = 0.f, A = 0.f, B = 0.f;
    #pragma unroll
    for (int k = 0; k < 8; ++k) {
        const int t = grp * 8 + k;
        S += g_ps[t * N_ROWS + row];
        A += g_pa[t * N_ROWS + row];
        B += g_pb[t * N_ROWS + row];
    }
    __shared__ float ss[8][32], sa[8][32], sb2[8][32];
    ss[grp][rlane] = S; sa[grp][rlane] = A; sb2[grp][rlane] = B;
    __syncthreads();
    if (grp == 0) {
        float St = 0.f, At = 0.f, Bt = 0.f;
        #pragma unroll
        for (int g = 0; g < 8; ++g) {
            St += ss[g][rlane]; At += sa[g][rlane]; Bt += sb2[g][rlane];
        }
        // loss_i = lse_i * B_i - A_i   (no max shift: |sim| <= ~5)
        float loss = logf(St) * Bt - At;
        #pragma unroll
        for (int o = 16; o > 0; o >>= 1) loss += __shfl_xor_sync(0xffffffffu, loss, o);

        unsigned last = 0;
        if (rlane == 0) {
            g_blocksum[blockIdx.x] = loss;
            __threadfence();                            // publish before counting
            unsigned old = atomicAdd(&g_done, 1u);
            last = (old == NRL_CTAS - 1) ? 1u : 0u;
        }
        last = __shfl_sync(0xffffffffu, last, 0);
        if (last) {
            __threadfence();                            // acquire all partials
            float v = 0.f;
            #pragma unroll
            for (int i = 0; i < NRL_CTAS / 32; ++i)     // fixed per-lane order
                v += g_blocksum[rlane + i * 32];
            #pragma unroll
            for (int o = 16; o > 0; o >>= 1) v += __shfl_xor_sync(0xffffffffu, v, o);
            if (rlane == 0) {
                out[0] = v * (1.0f / (float)N_ROWS);
                g_done = 0;                             // reset for next graph replay
            }
        }
    }
}

// ------------------------------------------------------------------
// Launcher (graph-capturable)
// ------------------------------------------------------------------
extern "C" void kernel_launch(void* const* d_in, const int* in_sizes, int n_in,
                              void* d_out, int out_size) {
    const float* embs   = (const float*)d_in[0];
    const float* labels = (const float*)d_in[1];
    if (n_in >= 2 && in_sizes[0] == N_ROWS * N_ROWS) {  // defensive input-order check
        const float* tmp = embs; embs = labels; labels = tmp;
    }
    float* out = (float*)d_out;

    cudaFuncSetAttribute(coref_main_kernel,
                         cudaFuncAttributeMaxDynamicSharedMemorySize, SMEM_BYTES);

    coref_norm_kernel<<<N_ROWS / 8, 256>>>(embs);
    coref_main_kernel<<<NTRI, THREADS, SMEM_BYTES>>>(labels);
    coref_rowloss_kernel<<<NRL_CTAS, 256>>>(out);
}